// round 15
// baseline (speedup 1.0000x reference)
#include <cuda_runtime.h>
#include <cuda_fp16.h>
#include <math.h>
#include <stdint.h>

#define NN 50000
#define NE 800000
#define HD 256
#define K2 512
#define NEXP 8
#define NG 64
#define LIST_SZ (NN + NEXP*128)
#define MT 391           /* ceil(50000/128) */
#define FIXCAP 16384

// ---------------- scratch (static device globals; no allocation) ----------------
static __device__ float g_h[(size_t)NN*HD];
static __device__ float g_sf[(size_t)NN*2];
static __device__ int   g_src[NE];
static __device__ int   g_dst[NE];
static __device__ int   g_batch[NN];
static __device__ float g_ncnt[NG];
static __device__ float g_ecnt[NG];
static __device__ int   g_idx[NN];
static __device__ int   g_cnt[NEXP];
static __device__ int   g_cursor[NEXP];
static __device__ int   g_poff[NEXP+1];
static __device__ int   g_list[LIST_SZ];
static __device__ int   g_is64;
static __device__ int   g_deg[NN];
static __device__ int   g_rowptr[NN+1];
static __device__ int   g_wcur[NN];
static __device__ int   g_csrc[NE];
static __device__ int   g_fixn;
static __device__ int   g_fixlist[FIXCAP];
static __device__ __half g_w16[(size_t)2*NEXP*HD*K2];   // [layer][expert][n][k] K-major fp16
static __device__ __half g_wr1hi[(size_t)HD*HD];        // router Wr1 [n][k] K-major split
static __device__ __half g_wr1lo[(size_t)HD*HD];
static __device__ __half gA1hi[(size_t)NN*K2];          // [node][512] = [h|aggh] hi
static __device__ __half gA1lo[(size_t)NN*K2];          // lo
static __device__ __half gZhi[(size_t)NEXP*NN*HD];      // [e][node][256] hi
static __device__ __half gZlo[(size_t)NEXP*NN*HD];      // lo
static __device__ __half gG2hi[(size_t)NN*HD];          // agg2 hi
static __device__ __half gG2lo[(size_t)NN*HD];          // agg2 lo

// ================= PTX helpers (arch-agnostic: sm_80+ only) =================
__device__ __forceinline__ uint32_t smem_u32(const void* p) {
    uint32_t a;
    asm("{ .reg .u64 t; cvta.to.shared.u64 t, %1; cvt.u32.u64 %0, t; }" : "=r"(a) : "l"(p));
    return a;
}
#define CP16(dst, src) \
    asm volatile("cp.async.cg.shared.global [%0], [%1], 16;" :: "r"(dst), "l"(src) : "memory")
#define CP_COMMIT()  asm volatile("cp.async.commit_group;" ::: "memory")
#define CP_WAIT1()   asm volatile("cp.async.wait_group 1;" ::: "memory")
#define CP_WAIT2()   asm volatile("cp.async.wait_group 2;" ::: "memory")

#define LDSM4(r0, r1, r2, r3, addr) \
    asm volatile("ldmatrix.sync.aligned.m8n8.x4.shared.b16 {%0,%1,%2,%3}, [%4];" \
                 : "=r"(r0), "=r"(r1), "=r"(r2), "=r"(r3) : "r"(addr))

__device__ __forceinline__ void mma16816(float* c, const uint32_t* a, uint32_t b0, uint32_t b1) {
    asm volatile(
        "mma.sync.aligned.m16n8k16.row.col.f32.f16.f16.f32 "
        "{%0,%1,%2,%3}, {%4,%5,%6,%7}, {%8,%9}, {%0,%1,%2,%3};"
        : "+f"(c[0]), "+f"(c[1]), "+f"(c[2]), "+f"(c[3])
        : "r"(a[0]), "r"(a[1]), "r"(a[2]), "r"(a[3]), "r"(b0), "r"(b1));
}

// 64B-row swizzle: element (row, 16B-chunk ch) -> row*64 + (ch ^ ((row>>1)&3))*16
__device__ __forceinline__ uint32_t sw64(int row, int ch) {
    return (uint32_t)row*64u + (uint32_t)((ch ^ ((row >> 1) & 3)) << 4);
}

__device__ __forceinline__ uint32_t pack2(float x, float y) {
    return ((uint32_t)__half_as_ushort(__float2half_rn(y)) << 16)
         | __half_as_ushort(__float2half_rn(x));
}
__device__ __forceinline__ uint32_t pack_lo2(float x, float y) {
    float rx = x - __half2float(__float2half_rn(x));
    float ry = y - __half2float(__float2half_rn(y));
    return ((uint32_t)__half_as_ushort(__float2half_rn(ry)) << 16)
         | __half_as_ushort(__float2half_rn(rx));
}
__device__ __forceinline__ void split_store(__half* hi, __half* lo, float v) {
    __half h = __float2half_rn(v);
    *hi = h;
    *lo = __float2half_rn(v - __half2float(h));
}

// ---------------- dtype detect + convert (+ fused degree histogram) ----------------
__global__ void detect_kernel(const unsigned int* ei) {
    if (threadIdx.x == 0 && blockIdx.x == 0) {
        int flag = 1;
        for (int j = 0; j < 64; j++)
            if (ei[2*j + 1] != 0u) { flag = 0; break; }
        g_is64 = flag;
    }
}

__global__ void convert_kernel(const void* ei, const void* batch) {
    int is64 = g_is64;
    int stride = gridDim.x * blockDim.x;
    int tid = blockIdx.x * blockDim.x + threadIdx.x;
    if (is64) {
        const long long* e64 = (const long long*)ei;
        const long long* b64 = (const long long*)batch;
        for (int i = tid; i < NE; i += stride) {
            int d = (int)e64[NE + i];
            g_src[i] = (int)e64[i];
            g_dst[i] = d;
            atomicAdd(&g_deg[d], 1);
        }
        for (int i = tid; i < NN; i += stride) g_batch[i] = (int)b64[i];
    } else {
        const int* e32 = (const int*)ei;
        const int* b32 = (const int*)batch;
        for (int i = tid; i < NE; i += stride) {
            int d = e32[NE + i];
            g_src[i] = e32[i];
            g_dst[i] = d;
            atomicAdd(&g_deg[d], 1);
        }
        for (int i = tid; i < NN; i += stride) g_batch[i] = b32[i];
    }
}

// ---------------- init ----------------
__global__ void init_kernel() {
    int stride = gridDim.x * blockDim.x;
    int tid = blockIdx.x * blockDim.x + threadIdx.x;
    for (int i = tid; i < LIST_SZ; i += stride) g_list[i] = -1;
    for (int i = tid; i < NN; i += stride) g_deg[i] = 0;
    if (tid < NG) { g_ncnt[tid] = 0.f; g_ecnt[tid] = 0.f; }
    if (tid < NEXP) g_cnt[tid] = 0;
    if (tid == 0) g_fixn = 0;
}

// ---------------- encoder: h + split write of A1 h-half ----------------
__global__ void encoder_kernel(const float* __restrict__ x,
                               const float* __restrict__ W,
                               const float* __restrict__ b) {
    __shared__ float Ws[6*HD];
    for (int i = threadIdx.x; i < 6*HD; i += blockDim.x) Ws[i] = W[i];
    __syncthreads();
    int n = threadIdx.x;
    float bn = b[n];
    for (int row = blockIdx.x; row < NN; row += gridDim.x) {
        float x0 = x[row*6+0], x1 = x[row*6+1], x2 = x[row*6+2];
        float x3 = x[row*6+3], x4 = x[row*6+4], x5 = x[row*6+5];
        float s = bn;
        s += x0 * Ws[0*HD+n]; s += x1 * Ws[1*HD+n]; s += x2 * Ws[2*HD+n];
        s += x3 * Ws[3*HD+n]; s += x4 * Ws[4*HD+n]; s += x5 * Ws[5*HD+n];
        float h = fmaxf(s, 0.f);
        g_h[(size_t)row*HD + n] = h;
        split_store(gA1hi + (size_t)row*K2 + n, gA1lo + (size_t)row*K2 + n, h);
    }
}

// ---------------- CSR build ----------------
__global__ void scan_kernel() {
    __shared__ int part[1024];
    const int CH = (NN + 1023) / 1024;
    int t = threadIdx.x;
    int base = t * CH;
    int sum = 0;
    for (int i = 0; i < CH; i++) {
        int n = base + i;
        if (n < NN) sum += g_deg[n];
    }
    part[t] = sum;
    __syncthreads();
    for (int off = 1; off < 1024; off <<= 1) {
        int v = (t >= off) ? part[t - off] : 0;
        __syncthreads();
        part[t] += v;
        __syncthreads();
    }
    int run = (t == 0) ? 0 : part[t - 1];
    for (int i = 0; i < CH; i++) {
        int n = base + i;
        if (n < NN) {
            g_rowptr[n] = run;
            g_wcur[n] = run;
            run += g_deg[n];
        }
    }
    if (t == 0) g_rowptr[NN] = NE;
}

__global__ void scatter_kernel() {
    int stride = gridDim.x * blockDim.x;
    for (int i = blockIdx.x * blockDim.x + threadIdx.x; i < NE; i += stride) {
        int d = g_dst[i];
        int pos = atomicAdd(&g_wcur[d], 1);
        g_csrc[pos] = g_src[i];
    }
}

// ---------------- aggh: A@h (fp16-hi gathers, deg-averaged quant) -> split write ----
__global__ void aggh_kernel() {
    int nwarps = (gridDim.x * blockDim.x) >> 5;
    int w = (blockIdx.x * blockDim.x + threadIdx.x) >> 5;
    int lane = threadIdx.x & 31;
    for (int u = w; u < 2*NN; u += nwarps) {
        int node = u >> 1;
        int c0 = (u & 1) * 128 + lane * 4;
        float a0 = 0.f, a1 = 0.f, a2 = 0.f, a3 = 0.f;
        int b = g_rowptr[node], en = g_rowptr[node+1];
        for (int p = b; p < en; p++) {
            uint2 vh = *(const uint2*)(gA1hi + (size_t)g_csrc[p]*K2 + c0);
            float2 h0 = __half22float2(*(__half2*)&vh.x);
            float2 h1 = __half22float2(*(__half2*)&vh.y);
            a0 += h0.x; a1 += h0.y; a2 += h1.x; a3 += h1.y;
        }
        size_t o = (size_t)node*K2 + 256 + c0;
        *(uint2*)(gA1hi + o) = make_uint2(pack2(a0, a1), pack2(a2, a3));
        *(uint2*)(gA1lo + o) = make_uint2(pack_lo2(a0, a1), pack_lo2(a2, a3));
    }
}

// ---------------- aggz over expert range [e0,e1): hi-only gathers -> split agg2 -----
__global__ void aggz_kernel(int e0, int e1) {
    int nwarps = (gridDim.x * blockDim.x) >> 5;
    int w = (blockIdx.x * blockDim.x + threadIdx.x) >> 5;
    int lane = threadIdx.x & 31;
    int u0 = 2 * g_poff[e0], u1 = 2 * g_poff[e1];
    for (int u = u0 + w; u < u1; u += nwarps) {
        int node = g_list[u >> 1];
        if (node < 0) continue;
        int c0 = (u & 1) * 128 + lane * 4;
        const __half* zh = gZhi + (size_t)g_idx[node]*NN*HD;
        float a0 = 0.f, a1 = 0.f, a2 = 0.f, a3 = 0.f;
        int b = g_rowptr[node], en = g_rowptr[node+1];
        for (int p = b; p < en; p++) {
            uint2 vh = *(const uint2*)(zh + (size_t)g_csrc[p]*HD + c0);
            float2 h0 = __half22float2(*(__half2*)&vh.x);
            float2 h1 = __half22float2(*(__half2*)&vh.y);
            a0 += h0.x; a1 += h0.y; a2 += h1.x; a3 += h1.y;
        }
        size_t o = (size_t)node*HD + c0;
        *(uint2*)(gG2hi + o) = make_uint2(pack2(a0, a1), pack2(a2, a3));
        *(uint2*)(gG2lo + o) = make_uint2(pack_lo2(a0, a1), pack_lo2(a2, a3));
    }
}

// ---------------- per-graph counts + size features ----------------
__global__ void counts_kernel() {
    __shared__ float sn[NG], se[NG];
    if (threadIdx.x < NG) { sn[threadIdx.x] = 0.f; se[threadIdx.x] = 0.f; }
    __syncthreads();
    int stride = gridDim.x * blockDim.x;
    int tid = blockIdx.x * blockDim.x + threadIdx.x;
    for (int i = tid; i < NN; i += stride) atomicAdd(&sn[g_batch[i]], 1.f);
    for (int i = tid; i < NE; i += stride) atomicAdd(&se[g_batch[g_src[i]]], 1.f);
    __syncthreads();
    if (threadIdx.x < NG) {
        atomicAdd(&g_ncnt[threadIdx.x], sn[threadIdx.x]);
        atomicAdd(&g_ecnt[threadIdx.x], se[threadIdx.x]);
    }
}

__global__ void sf_kernel() {
    int stride = gridDim.x * blockDim.x;
    for (int i = blockIdx.x * blockDim.x + threadIdx.x; i < NN; i += stride) {
        int b = g_batch[i];
        g_sf[2*i + 0] = log1pf(g_ncnt[b]);
        g_sf[2*i + 1] = log1pf(g_ecnt[b]);
    }
}

// ---------------- weight preps ----------------
__global__ void wprep_kernel(const float* __restrict__ Ws0, const float* __restrict__ Wn0,
                             const float* __restrict__ Ws1, const float* __restrict__ Wn1) {
    int stride = gridDim.x * blockDim.x;
    const int TOT = 2*NEXP*HD*K2;
    for (int i = blockIdx.x * blockDim.x + threadIdx.x; i < TOT; i += stride) {
        int k = i & 511;
        int n = (i >> 9) & 255;
        int e = (i >> 17) & 7;
        int l = i >> 20;
        const float* Wsrc = (l == 0) ? (k < 256 ? Ws0 : Wn0) : (k < 256 ? Ws1 : Wn1);
        int kk = k & 255;
        g_w16[i] = __float2half_rn(Wsrc[((size_t)e*256 + kk)*256 + n]);
    }
}

__global__ void wr1prep_kernel(const float* __restrict__ Wr1) {
    int stride = gridDim.x * blockDim.x;
    for (int i = blockIdx.x * blockDim.x + threadIdx.x; i < HD*HD; i += stride) {
        int k = i & 255, n = i >> 8;
        split_store(g_wr1hi + (size_t)n*HD + k, g_wr1lo + (size_t)n*HD + k,
                    Wr1[(size_t)k*HD + n]);
    }
}

// ---------------- tensor-core router: split-fp16 3-term + in-kernel argmax ----------
#define R2_STG 49152          /* Ahi 8K | Alo 8K | Bhi 16K | Blo 16K */
#define R2_OFF_LGP  98304
#define R2_OFF_WR2 102400
#define R2_OFF_BIAS 110592
#define R2_OFF_W2A 111616
#define R2_OFF_W2B 112640
#define R2_DSMEM  113664

__device__ __forceinline__ void issue_loads_r(uint32_t sb, int stage, int kt, int mbase, int t) {
    uint32_t stg = sb + stage*R2_STG;
    #pragma unroll
    for (int q = 0; q < 2; q++) {     // A hi+lo: 1024 x 16B
        int lin = q*512 + t;
        int split = lin >> 9;
        int rem = lin & 511;
        int row = rem >> 2, ch = rem & 3;
        int node = mbase + row; if (node >= NN) node = NN - 1;
        const __half* src = (split ? gA1lo : gA1hi) + (size_t)node*K2 + kt*32 + ch*8;
        CP16(stg + split*8192 + sw64(row, ch), src);
    }
    #pragma unroll
    for (int q = 0; q < 4; q++) {     // B hi+lo: 2048 x 16B
        int lin = q*512 + t;
        int split = lin >> 10;
        int rem = lin & 1023;
        int n = rem >> 2, ch = rem & 3;
        const __half* src = (split ? g_wr1lo : g_wr1hi) + (size_t)n*HD + kt*32 + ch*8;
        CP16(stg + 16384 + split*16384 + sw64(n, ch), src);
    }
    CP_COMMIT();
}

__device__ __forceinline__ void mma_all4(float acc[4][4][4], uint32_t aF[4][4], uint32_t bF[2][4]) {
    #pragma unroll
    for (int mf = 0; mf < 4; mf++)
        #pragma unroll
        for (int nf = 0; nf < 4; nf++)
            mma16816(acc[mf][nf], aF[mf], bF[nf >> 1][(nf & 1)*2 + 0], bF[nf >> 1][(nf & 1)*2 + 1]);
}

__global__ void __launch_bounds__(512, 1) router_mma_kernel(
    const float* __restrict__ Wr1, const float* __restrict__ br1,
    const float* __restrict__ Wr2, const float* __restrict__ br2) {
    extern __shared__ char smem[];
    uint32_t sb = smem_u32(smem);
    int t = threadIdx.x;
    float* lgpS  = (float*)(smem + R2_OFF_LGP);    // [128][8]
    float* Wr2s  = (float*)(smem + R2_OFF_WR2);    // [256][8]
    float* biasS = (float*)(smem + R2_OFF_BIAS);
    float* w2aS  = (float*)(smem + R2_OFF_W2A);
    float* w2bS  = (float*)(smem + R2_OFF_W2B);
    int mbase = blockIdx.x * 128;

    issue_loads_r(sb, 0, 0, mbase, t);
    issue_loads_r(sb, 1, 1, mbase, t);

    if (t < 256) {
        biasS[t] = br1[t];
        w2aS[t] = Wr1[256*HD + t];
        w2bS[t] = Wr1[257*HD + t];
    }
    for (int i = t; i < 256*8; i += 512) Wr2s[i] = Wr2[i];
    for (int i = t; i < 128*8; i += 512) lgpS[i] = 0.f;

    float acc[4][4][4];
    #pragma unroll
    for (int mf = 0; mf < 4; mf++)
        #pragma unroll
        for (int nf = 0; nf < 4; nf++)
            #pragma unroll
            for (int c = 0; c < 4; c++) acc[mf][nf][c] = 0.f;

    int lane = t & 31, wid = t >> 5;
    int m0 = (wid >> 3) * 64;
    int n0 = (wid & 7) * 32;

    for (int kt = 0; kt < 8; kt++) {
        CP_WAIT1();
        __syncthreads();
        uint32_t stg = sb + (kt & 1)*R2_STG;
        #pragma unroll
        for (int k16 = 0; k16 < 2; k16++) {
            uint32_t aF[4][4], bF[2][4];
            int akk = k16*16 + (lane >> 4)*8;
            int arow = lane & 15;
            int bg = lane >> 3, brr = lane & 7;
            int bkk = k16*16 + (bg & 1)*8;
            #pragma unroll
            for (int nf2 = 0; nf2 < 2; nf2++) {
                int row = n0 + nf2*16 + ((bg >> 1) & 1)*8 + brr;
                LDSM4(bF[nf2][0], bF[nf2][1], bF[nf2][2], bF[nf2][3],
                      stg + 16384 + sw64(row, bkk >> 3));
            }
            #pragma unroll
            for (int mf = 0; mf < 4; mf++) {
                int row = m0 + mf*16 + arow;
                LDSM4(aF[mf][0], aF[mf][1], aF[mf][2], aF[mf][3], stg + sw64(row, akk >> 3));
            }
            mma_all4(acc, aF, bF);                       // Ahi * Bhi
            #pragma unroll
            for (int mf = 0; mf < 4; mf++) {
                int row = m0 + mf*16 + arow;
                LDSM4(aF[mf][0], aF[mf][1], aF[mf][2], aF[mf][3], stg + 8192 + sw64(row, akk >> 3));
            }
            mma_all4(acc, aF, bF);                       // Alo * Bhi
            #pragma unroll
            for (int nf2 = 0; nf2 < 2; nf2++) {
                int row = n0 + nf2*16 + ((bg >> 1) & 1)*8 + brr;
                LDSM4(bF[nf2][0], bF[nf2][1], bF[nf2][2], bF[nf2][3],
                      stg + 32768 + sw64(row, bkk >> 3));
            }
            #pragma unroll
            for (int mf = 0; mf < 4; mf++) {
                int row = m0 + mf*16 + arow;
                LDSM4(aF[mf][0], aF[mf][1], aF[mf][2], aF[mf][3], stg + sw64(row, akk >> 3));
            }
            mma_all4(acc, aF, bF);                       // Ahi * Blo
        }
        __syncthreads();
        if (kt + 2 < 8) issue_loads_r(sb, kt & 1, kt + 2, mbase, t);
        else CP_COMMIT();
    }

    // epilogue: relu'd r -> partial logits -> smem reduction
    #pragma unroll
    for (int mf = 0; mf < 4; mf++)
        #pragma unroll
        for (int p = 0; p < 2; p++) {
            int rloc = m0 + mf*16 + (lane >> 2) + p*8;
            int node = mbase + rloc;
            float sf0 = 0.f, sf1 = 0.f;
            if (node < NN) { sf0 = g_sf[2*node]; sf1 = g_sf[2*node + 1]; }
            float lp[NEXP];
            #pragma unroll
            for (int e = 0; e < NEXP; e++) lp[e] = 0.f;
            #pragma unroll
            for (int nf = 0; nf < 4; nf++)
                #pragma unroll
                for (int q = 0; q < 2; q++) {
                    int col = n0 + nf*8 + (lane & 3)*2 + q;
                    float r = acc[mf][nf][p*2+q] + sf0*w2aS[col] + sf1*w2bS[col] + biasS[col];
                    r = fmaxf(r, 0.f);
                    const float* wr = Wr2s + col*8;
                    #pragma unroll
                    for (int e = 0; e < NEXP; e++) lp[e] += r * wr[e];
                }
            #pragma unroll
            for (int off = 1; off < 4; off <<= 1)
                #pragma unroll
                for (int e = 0; e < NEXP; e++) lp[e] += __shfl_xor_sync(0xFFFFFFFFu, lp[e], off);
            if ((lane & 3) == 0 && node < NN) {
                #pragma unroll
                for (int e = 0; e < NEXP; e++) atomicAdd(&lgpS[rloc*8 + e], lp[e]);
            }
        }
    __syncthreads();

    if (t < 128) {
        int node = mbase + t;
        if (node < NN) {
            float v0 = lgpS[t*8 + 0] + br2[0];
            int best = 0; float bv = v0, second = -1e30f;
            #pragma unroll
            for (int e = 1; e < NEXP; e++) {
                float v = lgpS[t*8 + e] + br2[e];
                if (v > bv) { second = bv; bv = v; best = e; }
                else if (v > second) second = v;
            }
            g_idx[node] = best;
            if (bv - second < 1e-3f * fmaxf(fabsf(bv), 1.f)) {
                int pos = atomicAdd(&g_fixn, 1);
                if (pos < FIXCAP) g_fixlist[pos] = node;
            }
        }
    }
}

// ---------------- exact fp32 fixup for near-tie nodes ----------------
__global__ void fixup_kernel(const float* __restrict__ Wr1, const float* __restrict__ br1,
                             const float* __restrict__ Wr2, const float* __restrict__ br2) {
    int nwarps = (gridDim.x * blockDim.x) >> 5;
    int w = (blockIdx.x * blockDim.x + threadIdx.x) >> 5;
    int lane = threadIdx.x & 31;
    int n = g_fixn; if (n > FIXCAP) n = FIXCAP;
    for (int f = w; f < n; f += nwarps) {
        int node = g_fixlist[f];
        float hreg[8];
        #pragma unroll
        for (int j = 0; j < 8; j++) hreg[j] = g_h[(size_t)node*HD + j*32 + lane];
        float r[8];
        #pragma unroll
        for (int j = 0; j < 8; j++) r[j] = 0.f;
        for (int k = 0; k < 256; k++) {
            float hk = __shfl_sync(0xFFFFFFFFu, hreg[k >> 5], k & 31);
            const float* wrow = Wr1 + (size_t)k*HD + lane;
            #pragma unroll
            for (int j = 0; j < 8; j++) r[j] += hk * wrow[j*32];
        }
        float sf0 = g_sf[2*node], sf1 = g_sf[2*node + 1];
        float lp[NEXP];
        #pragma unroll
        for (int e = 0; e < NEXP; e++) lp[e] = 0.f;
        #pragma unroll
        for (int j = 0; j < 8; j++) {
            int col = j*32 + lane;
            float rv = r[j] + sf0*Wr1[256*HD + col] + sf1*Wr1[257*HD + col] + br1[col];
            rv = fmaxf(rv, 0.f);
            #pragma unroll
            for (int e = 0; e < NEXP; e++) lp[e] += rv * Wr2[col*8 + e];
        }
        #pragma unroll
        for (int off = 16; off > 0; off >>= 1)
            #pragma unroll
            for (int e = 0; e < NEXP; e++) lp[e] += __shfl_xor_sync(0xFFFFFFFFu, lp[e], off);
        if (lane == 0) {
            int best = 0; float bv = lp[0] + br2[0];
            #pragma unroll
            for (int e = 1; e < NEXP; e++) {
                float v = lp[e] + br2[e];
                if (v > bv) { bv = v; best = e; }
            }
            g_idx[node] = best;
        }
    }
}

// ---------------- bucket nodes by expert (padded to 128) ----------------
__global__ void bucket_count_kernel() {
    __shared__ int sc[NEXP];
    if (threadIdx.x < NEXP) sc[threadIdx.x] = 0;
    __syncthreads();
    int stride = gridDim.x * blockDim.x;
    for (int i = blockIdx.x * blockDim.x + threadIdx.x; i < NN; i += stride)
        atomicAdd(&sc[g_idx[i]], 1);
    __syncthreads();
    if (threadIdx.x < NEXP) atomicAdd(&g_cnt[threadIdx.x], sc[threadIdx.x]);
}

__global__ void bucket_scan_kernel() {
    if (threadIdx.x == 0 && blockIdx.x == 0) {
        int off = 0;
        for (int e = 0; e < NEXP; e++) {
            g_poff[e] = off;
            g_cursor[e] = off;
            off += ((g_cnt[e] + 127) / 128) * 128;
        }
        g_poff[NEXP] = off;
    }
}

__global__ void bucket_scatter_kernel() {
    int stride = gridDim.x * blockDim.x;
    for (int i = blockIdx.x * blockDim.x + threadIdx.x; i < NN; i += stride) {
        int pos = atomicAdd(&g_cursor[g_idx[i]], 1);
        g_list[pos] = i;
    }
}

// ---------------- fp16 2-term tensor-core GEMM, 512 threads, expert-range ----------
#define STGSZ 32768          /* per-stage: Ahi 8K | Alo 8K | B 16K */
#define NSTG 3
#define OFF_ROWS 98304
#define OFF_BIAS 98816
#define DSMEM    99840

__device__ __forceinline__ void issue_loads(uint32_t sb, int stage, int kt, int layer, int e,
                                            const int* rowsS, int t) {
    uint32_t stg = sb + stage*STGSZ;
    #pragma unroll
    for (int q = 0; q < 2; q++) {     // A hi+lo: 1024 x 16B over 512 threads
        int lin = q*512 + t;
        int split = lin >> 9;
        int rem = lin & 511;
        int row = rem >> 2, ch = rem & 3;
        int node = rowsS[row]; if (node < 0) node = 0;
        const __half* src;
        if (layer == 0) {
            src = (split ? gA1lo : gA1hi) + (size_t)node*K2 + kt*32 + ch*8;
        } else {
            int k0 = kt*32;
            if (k0 < 256) src = (split ? gZlo : gZhi) + ((size_t)e*NN + node)*HD + k0 + ch*8;
            else          src = (split ? gG2lo : gG2hi) + (size_t)node*HD + (k0 - 256) + ch*8;
        }
        CP16(stg + split*8192 + sw64(row, ch), src);
    }
    #pragma unroll
    for (int q = 0; q < 2; q++) {     // B: 1024 x 16B over 512 threads
        int lin = q*512 + t;
        int n = lin >> 2, ch = lin & 3;
        const __half* src = g_w16
            + ((size_t)((layer*NEXP + e)*256 + n))*K2 + kt*32 + ch*8;
        CP16(stg + 16384 + sw64(n, ch), src);
    }
    CP_COMMIT();
}

__global__ void __launch_bounds__(512, 1) moe_mma_kernel(
    const float* __restrict__ bias_base, int layer, int e0,
    float* __restrict__ outL2) {
    extern __shared__ char smem[];
    uint32_t sb = smem_u32(smem);
    int t = threadIdx.x;
    int* rowsS = (int*)(smem + OFF_ROWS);
    float* biasS = (float*)(smem + OFF_BIAS);

    int e;
    if (layer == 0) {
        e = e0 + (blockIdx.x & 3);          // 4-expert-inner: A tile L2-shared
        int mtile = blockIdx.x >> 2;
        if (t < 128) {
            int m = mtile * 128 + t;
            rowsS[t] = (m < NN) ? m : -1;
        }
    } else {
        int mstart = g_poff[e0];
        int mb = mstart + blockIdx.x * 128;
        if (mb >= g_poff[e0 + 4]) return;
        int ee = e0;
        while (mb >= g_poff[ee + 1]) ee++;
        e = ee;
        if (t < 128) rowsS[t] = g_list[mb + t];
    }
    if (t < 256) biasS[t] = bias_base[e*HD + t];
    __syncthreads();

    float acc[4][4][4];
    #pragma unroll
    for (int mf = 0; mf < 4; mf++)
        #pragma unroll
        for (int nf = 0; nf < 4; nf++)
            #pragma unroll
            for (int c = 0; c < 4; c++) acc[mf][nf][c] = 0.f;

    int lane = t & 31, wid = t >> 5;
    int m0 = (wid >> 3) * 64;      // 2 m-warps
    int n0 = (wid & 7) * 32;       // 8 n-warps

    issue_loads(sb, 0, 0, layer, e, rowsS, t);
    issue_loads(sb, 1, 1, layer, e, rowsS, t);
    issue_loads(sb, 2, 2, layer, e, rowsS, t);

    for (int kt = 0; kt < 16; kt++) {
        CP_WAIT2();
        __syncthreads();
        uint32_t stg = sb + (kt % NSTG)*STGSZ;
        #pragma unroll
        for (int k16 = 0; k16 < 2; k16++) {
            uint32_t aF[4][4], bF[2][4];
            int akk = k16*16 + (lane >> 4)*8;
            int arow = lane & 15;
            int bg = lane >> 3, brr = lane & 7;
            int bkk = k16*16 + (bg & 1)*8;
            #pragma unroll
            for (int nf2 = 0; nf2 < 2; nf2++) {
                int row = n0 + nf2*16 + ((bg >> 1) & 1)*8 + brr;
                LDSM4(bF[nf2][0], bF[nf2][1], bF[nf2][2], bF[nf2][3],
                      stg + 16384 + sw64(row, bkk >> 3));
            }
            #pragma unroll
            for (int mf = 0; mf < 4; mf++) {
                int row = m0 + mf*16 + arow;
                LDSM4(aF[mf][0], aF[mf][1], aF[mf][2], aF[mf][3], stg + sw64(row, akk >> 3));
            }
            mma_all4(acc, aF, bF);                       // Ahi * B
            #pragma unroll
            for (int mf = 0; mf < 4; mf++) {
                int row = m0 + mf*16 + arow;
                LDSM4(aF[mf][0], aF[mf][1], aF[mf][2], aF[mf][3], stg + 8192 + sw64(row, akk >> 3));
            }
            mma_all4(acc, aF, bF);                       // Alo * B
        }
        __syncthreads();
        if (kt + NSTG < 16) issue_loads(sb, kt % NSTG, kt + NSTG, layer, e, rowsS, t);
        else CP_COMMIT();
    }

    // ---------------- epilogue ----------------
    if (layer == 0) {
        #pragma unroll
        for (int mf = 0; mf < 4; mf++)
            #pragma unroll
            for (int p = 0; p < 2; p++) {
                int row = m0 + mf*16 + (lane >> 2) + p*8;
                int node = rowsS[row];
                if (node < 0) continue;
                size_t base = ((size_t)e*NN + node)*HD;
                #pragma unroll
                for (int nf = 0; nf < 4; nf++) {
                    int col = n0 + nf*8 + (lane & 3)*2;
                    float z0 = fmaxf(acc[mf][nf][p*2+0] + biasS[col],     0.f);
                    float z1 = fmaxf(acc[mf][nf][p*2+1] + biasS[col + 1], 0.f);
                    *(uint32_t*)(gZhi + base + col) = pack2(z0, z1);
                    *(uint32_t*)(gZlo + base + col) = pack_lo2(z0, z1);
                }
            }
    } else {
        #pragma unroll
        for (int mf = 0; mf < 4; mf++)
            #pragma unroll
            for (int p = 0; p < 2; p++) {
                int row = m0 + mf*16 + (lane >> 2) + p*8;
                int node = rowsS[row];
                if (node < 0) continue;
                float* orow = outL2 + (size_t)node*HD;
                #pragma unroll
                for (int nf = 0; nf < 4; nf++) {
                    int col = n0 + nf*8 + (lane & 3)*2;
                    float o0 = acc[mf][nf][p*2+0] + biasS[col];
                    float o1 = acc[mf][nf][p*2+1] + biasS[col + 1];
                    *(float2*)(orow + col) = make_float2(o0, o1);
                }
            }
    }
}

// ---------------- launch: CSR under encoder; expert-halved tail pipeline ----------
extern "C" void kernel_launch(void* const* d_in, const int* in_sizes, int n_in,
                              void* d_out, int out_size) {
    (void)in_sizes; (void)n_in; (void)out_size;
    const float* x     = (const float*)d_in[0];
    const void*  ei    = d_in[1];
    const void*  batch = d_in[2];
    const float* W_enc = (const float*)d_in[3];
    const float* b_enc = (const float*)d_in[4];
    const float* Wr1   = (const float*)d_in[5];
    const float* br1   = (const float*)d_in[6];
    const float* Wr2   = (const float*)d_in[7];
    const float* br2   = (const float*)d_in[8];
    const float* Ws0   = (const float*)d_in[9];
    const float* Wn0   = (const float*)d_in[10];
    const float* b0    = (const float*)d_in[11];
    const float* Ws1   = (const float*)d_in[12];
    const float* Wn1   = (const float*)d_in[13];
    const float* b1    = (const float*)d_in[14];
    float* out = (float*)d_out;

    static cudaStream_t s1 = nullptr;
    static cudaEvent_t evCvt, evEnc, evCSR, evW, evB, evZa;
    if (!s1) {
        cudaStreamCreateWithFlags(&s1, cudaStreamNonBlocking);
        cudaEventCreateWithFlags(&evCvt, cudaEventDisableTiming);
        cudaEventCreateWithFlags(&evEnc, cudaEventDisableTiming);
        cudaEventCreateWithFlags(&evCSR, cudaEventDisableTiming);
        cudaEventCreateWithFlags(&evW,   cudaEventDisableTiming);
        cudaEventCreateWithFlags(&evB,   cudaEventDisableTiming);
        cudaEventCreateWithFlags(&evZa,  cudaEventDisableTiming);
        cudaFuncSetAttribute(moe_mma_kernel,
                             cudaFuncAttributeMaxDynamicSharedMemorySize, DSMEM);
        cudaFuncSetAttribute(router_mma_kernel,
                             cudaFuncAttributeMaxDynamicSharedMemorySize, R2_DSMEM);
    }

    // main: detect -> init -> convert(+hist)
    detect_kernel<<<1, 32>>>((const unsigned int*)ei);
    init_kernel<<<512, 256>>>();
    convert_kernel<<<2048, 256>>>(ei, batch);
    cudaEventRecord(evCvt, 0);

    // side: CSR build under encoder, then weight prep, then router chain
    cudaStreamWaitEvent(s1, evCvt, 0);
    scan_kernel<<<1, 1024, 0, s1>>>();
    scatter_kernel<<<1024, 256, 0, s1>>>();
    cudaEventRecord(evCSR, s1);
    wprep_kernel<<<2048, 256, 0, s1>>>(Ws0, Wn0, Ws1, Wn1);
    cudaEventRecord(evW, s1);
    wr1prep_kernel<<<256, 256, 0, s1>>>(Wr1);

    // main: encoder (parallel with CSR build)
    encoder_kernel<<<2048, 256>>>(x, W_enc, b_enc);
    cudaEventRecord(evEnc, 0);

    // side: router chain (needs h)
    cudaStreamWaitEvent(s1, evEnc, 0);
    counts_kernel<<<512, 256, 0, s1>>>();
    sf_kernel<<<256, 256, 0, s1>>>();
    router_mma_kernel<<<MT, 512, R2_DSMEM, s1>>>(Wr1, br1, Wr2, br2);
    fixup_kernel<<<64, 256, 0, s1>>>(Wr1, br1, Wr2, br2);
    bucket_count_kernel<<<512, 256, 0, s1>>>();
    bucket_scan_kernel<<<1, 1, 0, s1>>>();
    bucket_scatter_kernel<<<256, 256, 0, s1>>>();
    cudaEventRecord(evB, s1);

    // main: aggh (needs CSR + h)
    cudaStreamWaitEvent(0, evCSR, 0);
    aggh_kernel<<<6250, 256>>>();

    // main: layer-1 first half (experts 0-3), then second half
    cudaStreamWaitEvent(0, evW, 0);
    moe_mma_kernel<<<MT*4, 512, DSMEM>>>(b0, 0, 0, nullptr);
    cudaEventRecord(evZa, 0);
    moe_mma_kernel<<<MT*4, 512, DSMEM>>>(b0, 0, 4, nullptr);

    // side: aggz + GEMM2 for experts 0-3 (overlaps GEMM1 second half)
    cudaStreamWaitEvent(s1, evZa, 0);
    aggz_kernel<<<3000, 256, 0, s1>>>(0, 4);
    moe_mma_kernel<<<400, 512, DSMEM, s1>>>(b1, 1, 0, out);

    // main: aggz + GEMM2 for experts 4-7
    cudaStreamWaitEvent(0, evB, 0);
    aggz_kernel<<<3000, 256>>>(4, 8);
    moe_mma_kernel<<<400, 512, DSMEM>>>(b1, 1, 4, out);

    // join: main must not retire before side's GEMM2a (harness reads out)
    cudaEventRecord(evCvt, s1);        // reuse event as completion marker
    cudaStreamWaitEvent(0, evCvt, 0);
}

// round 16
// speedup vs baseline: 1.0413x; 1.0413x over previous
#include <cuda_runtime.h>
#include <cuda_fp16.h>
#include <math.h>
#include <stdint.h>

#define NN 50000
#define NE 800000
#define HD 256
#define K2 512
#define NEXP 8
#define NG 64
#define LIST_SZ (NN + NEXP*128)
#define MT 391           /* ceil(50000/128) */
#define FIXCAP 16384
#define NBS 98           /* ceil(50000/512) scan blocks */

// ---------------- scratch (static device globals; no allocation) ----------------
static __device__ float g_h[(size_t)NN*HD];
static __device__ float g_sf[(size_t)NN*2];
static __device__ int   g_src[NE];
static __device__ int   g_dst[NE];
static __device__ int   g_batch[NN];
static __device__ float g_ncnt[NG];
static __device__ float g_ecnt[NG];
static __device__ int   g_idx[NN];
static __device__ int   g_cnt[NEXP];
static __device__ int   g_cursor[NEXP];
static __device__ int   g_poff[NEXP+1];
static __device__ int   g_list[LIST_SZ];
static __device__ int   g_is64;
static __device__ int   g_deg[NN];
static __device__ int   g_rowptr[NN+1];
static __device__ int   g_wcur[NN];
static __device__ int   g_csrc[NE];
static __device__ int   g_fixn;
static __device__ int   g_fixlist[FIXCAP];
static __device__ int   g_bsum[NBS];
static __device__ int   g_boff[NBS];
static __device__ __half g_w16[(size_t)2*NEXP*HD*K2];   // [layer][expert][n][k] K-major fp16
static __device__ __half g_wr1hi[(size_t)HD*HD];        // router Wr1 [n][k] K-major split
static __device__ __half g_wr1lo[(size_t)HD*HD];
static __device__ __half gA1hi[(size_t)NN*K2];          // [node][512] = [h|aggh] hi
static __device__ __half gA1lo[(size_t)NN*K2];          // lo
static __device__ __half gZhi[(size_t)NEXP*NN*HD];      // [e][node][256] hi
static __device__ __half gZlo[(size_t)NEXP*NN*HD];      // lo
static __device__ __half gG2hi[(size_t)NN*HD];          // agg2 hi
static __device__ __half gG2lo[(size_t)NN*HD];          // agg2 lo

// ================= PTX helpers (arch-agnostic: sm_80+ only) =================
__device__ __forceinline__ uint32_t smem_u32(const void* p) {
    uint32_t a;
    asm("{ .reg .u64 t; cvta.to.shared.u64 t, %1; cvt.u32.u64 %0, t; }" : "=r"(a) : "l"(p));
    return a;
}
#define CP16(dst, src) \
    asm volatile("cp.async.cg.shared.global [%0], [%1], 16;" :: "r"(dst), "l"(src) : "memory")
#define CP_COMMIT()  asm volatile("cp.async.commit_group;" ::: "memory")
#define CP_WAIT1()   asm volatile("cp.async.wait_group 1;" ::: "memory")
#define CP_WAIT2()   asm volatile("cp.async.wait_group 2;" ::: "memory")

#define LDSM4(r0, r1, r2, r3, addr) \
    asm volatile("ldmatrix.sync.aligned.m8n8.x4.shared.b16 {%0,%1,%2,%3}, [%4];" \
                 : "=r"(r0), "=r"(r1), "=r"(r2), "=r"(r3) : "r"(addr))

__device__ __forceinline__ void mma16816(float* c, const uint32_t* a, uint32_t b0, uint32_t b1) {
    asm volatile(
        "mma.sync.aligned.m16n8k16.row.col.f32.f16.f16.f32 "
        "{%0,%1,%2,%3}, {%4,%5,%6,%7}, {%8,%9}, {%0,%1,%2,%3};"
        : "+f"(c[0]), "+f"(c[1]), "+f"(c[2]), "+f"(c[3])
        : "r"(a[0]), "r"(a[1]), "r"(a[2]), "r"(a[3]), "r"(b0), "r"(b1));
}

// 64B-row swizzle: element (row, 16B-chunk ch) -> row*64 + (ch ^ ((row>>1)&3))*16
__device__ __forceinline__ uint32_t sw64(int row, int ch) {
    return (uint32_t)row*64u + (uint32_t)((ch ^ ((row >> 1) & 3)) << 4);
}

__device__ __forceinline__ uint32_t pack2(float x, float y) {
    return ((uint32_t)__half_as_ushort(__float2half_rn(y)) << 16)
         | __half_as_ushort(__float2half_rn(x));
}
__device__ __forceinline__ uint32_t pack_lo2(float x, float y) {
    float rx = x - __half2float(__float2half_rn(x));
    float ry = y - __half2float(__float2half_rn(y));
    return ((uint32_t)__half_as_ushort(__float2half_rn(ry)) << 16)
         | __half_as_ushort(__float2half_rn(rx));
}
__device__ __forceinline__ void split_store(__half* hi, __half* lo, float v) {
    __half h = __float2half_rn(v);
    *hi = h;
    *lo = __float2half_rn(v - __half2float(h));
}

// ---------------- dtype detect + convert (+ fused degree histogram) ----------------
__global__ void detect_kernel(const unsigned int* ei) {
    if (threadIdx.x == 0 && blockIdx.x == 0) {
        int flag = 1;
        for (int j = 0; j < 64; j++)
            if (ei[2*j + 1] != 0u) { flag = 0; break; }
        g_is64 = flag;
    }
}

__global__ void convert_kernel(const void* ei, const void* batch) {
    int is64 = g_is64;
    int stride = gridDim.x * blockDim.x;
    int tid = blockIdx.x * blockDim.x + threadIdx.x;
    if (is64) {
        const long long* e64 = (const long long*)ei;
        const long long* b64 = (const long long*)batch;
        for (int i = tid; i < NE; i += stride) {
            int d = (int)e64[NE + i];
            g_src[i] = (int)e64[i];
            g_dst[i] = d;
            atomicAdd(&g_deg[d], 1);
        }
        for (int i = tid; i < NN; i += stride) g_batch[i] = (int)b64[i];
    } else {
        const int* e32 = (const int*)ei;
        const int* b32 = (const int*)batch;
        for (int i = tid; i < NE; i += stride) {
            int d = e32[NE + i];
            g_src[i] = e32[i];
            g_dst[i] = d;
            atomicAdd(&g_deg[d], 1);
        }
        for (int i = tid; i < NN; i += stride) g_batch[i] = b32[i];
    }
}

// ---------------- init ----------------
__global__ void init_kernel() {
    int stride = gridDim.x * blockDim.x;
    int tid = blockIdx.x * blockDim.x + threadIdx.x;
    for (int i = tid; i < LIST_SZ; i += stride) g_list[i] = -1;
    for (int i = tid; i < NN; i += stride) g_deg[i] = 0;
    if (tid < NG) { g_ncnt[tid] = 0.f; g_ecnt[tid] = 0.f; }
    if (tid < NEXP) g_cnt[tid] = 0;
    if (tid == 0) g_fixn = 0;
}

// ---------------- encoder: h + split write of A1 h-half ----------------
__global__ void encoder_kernel(const float* __restrict__ x,
                               const float* __restrict__ W,
                               const float* __restrict__ b) {
    __shared__ float Ws[6*HD];
    for (int i = threadIdx.x; i < 6*HD; i += blockDim.x) Ws[i] = W[i];
    __syncthreads();
    int n = threadIdx.x;
    float bn = b[n];
    for (int row = blockIdx.x; row < NN; row += gridDim.x) {
        float x0 = x[row*6+0], x1 = x[row*6+1], x2 = x[row*6+2];
        float x3 = x[row*6+3], x4 = x[row*6+4], x5 = x[row*6+5];
        float s = bn;
        s += x0 * Ws[0*HD+n]; s += x1 * Ws[1*HD+n]; s += x2 * Ws[2*HD+n];
        s += x3 * Ws[3*HD+n]; s += x4 * Ws[4*HD+n]; s += x5 * Ws[5*HD+n];
        float h = fmaxf(s, 0.f);
        g_h[(size_t)row*HD + n] = h;
        split_store(gA1hi + (size_t)row*K2 + n, gA1lo + (size_t)row*K2 + n, h);
    }
}

// ---------------- CSR build: 3-phase parallel scan ----------------
__global__ void scan_part_kernel() {       // NBS blocks x 512
    __shared__ int sh[512];
    int t = threadIdx.x;
    int n = blockIdx.x * 512 + t;
    int v = (n < NN) ? g_deg[n] : 0;
    sh[t] = v;
    __syncthreads();
    #pragma unroll
    for (int off = 1; off < 512; off <<= 1) {
        int y = (t >= off) ? sh[t - off] : 0;
        __syncthreads();
        sh[t] += y;
        __syncthreads();
    }
    if (n < NN) g_rowptr[n] = sh[t] - v;   // local exclusive
    if (t == 511) g_bsum[blockIdx.x] = sh[511];
}

__global__ void scan_top_kernel() {        // 1 block x 128
    __shared__ int sh[128];
    int t = threadIdx.x;
    int v = (t < NBS) ? g_bsum[t] : 0;
    sh[t] = v;
    __syncthreads();
    #pragma unroll
    for (int off = 1; off < 128; off <<= 1) {
        int y = (t >= off) ? sh[t - off] : 0;
        __syncthreads();
        sh[t] += y;
        __syncthreads();
    }
    if (t < NBS) g_boff[t] = sh[t] - v;
}

__global__ void scan_apply_kernel() {      // NBS blocks x 512
    int n = blockIdx.x * 512 + threadIdx.x;
    if (n < NN) {
        int r = g_rowptr[n] + g_boff[blockIdx.x];
        g_rowptr[n] = r;
        g_wcur[n] = r;
    }
    if (n == 0) g_rowptr[NN] = NE;
}

__global__ void scatter_kernel() {
    int stride = gridDim.x * blockDim.x;
    for (int i = blockIdx.x * blockDim.x + threadIdx.x; i < NE; i += stride) {
        int d = g_dst[i];
        int pos = atomicAdd(&g_wcur[d], 1);
        g_csrc[pos] = g_src[i];
    }
}

// ---------------- aggh: A@h (fp16-hi gathers, deg-averaged quant) -> split write ----
__global__ void aggh_kernel() {
    int nwarps = (gridDim.x * blockDim.x) >> 5;
    int w = (blockIdx.x * blockDim.x + threadIdx.x) >> 5;
    int lane = threadIdx.x & 31;
    for (int u = w; u < 2*NN; u += nwarps) {
        int node = u >> 1;
        int c0 = (u & 1) * 128 + lane * 4;
        float a0 = 0.f, a1 = 0.f, a2 = 0.f, a3 = 0.f;
        int b = g_rowptr[node], en = g_rowptr[node+1];
        for (int p = b; p < en; p++) {
            uint2 vh = *(const uint2*)(gA1hi + (size_t)g_csrc[p]*K2 + c0);
            float2 h0 = __half22float2(*(__half2*)&vh.x);
            float2 h1 = __half22float2(*(__half2*)&vh.y);
            a0 += h0.x; a1 += h0.y; a2 += h1.x; a3 += h1.y;
        }
        size_t o = (size_t)node*K2 + 256 + c0;
        *(uint2*)(gA1hi + o) = make_uint2(pack2(a0, a1), pack2(a2, a3));
        *(uint2*)(gA1lo + o) = make_uint2(pack_lo2(a0, a1), pack_lo2(a2, a3));
    }
}

// ---------------- aggz: hi-only gathers (deg-averaged quant) -> split agg2 ----------
__global__ void aggz_kernel() {
    int nwarps = (gridDim.x * blockDim.x) >> 5;
    int w = (blockIdx.x * blockDim.x + threadIdx.x) >> 5;
    int lane = threadIdx.x & 31;
    for (int u = w; u < 2*LIST_SZ; u += nwarps) {
        int node = g_list[u >> 1];
        if (node < 0) continue;
        int c0 = (u & 1) * 128 + lane * 4;
        const __half* zh = gZhi + (size_t)g_idx[node]*NN*HD;
        float a0 = 0.f, a1 = 0.f, a2 = 0.f, a3 = 0.f;
        int b = g_rowptr[node], en = g_rowptr[node+1];
        for (int p = b; p < en; p++) {
            uint2 vh = *(const uint2*)(zh + (size_t)g_csrc[p]*HD + c0);
            float2 h0 = __half22float2(*(__half2*)&vh.x);
            float2 h1 = __half22float2(*(__half2*)&vh.y);
            a0 += h0.x; a1 += h0.y; a2 += h1.x; a3 += h1.y;
        }
        size_t o = (size_t)node*HD + c0;
        *(uint2*)(gG2hi + o) = make_uint2(pack2(a0, a1), pack2(a2, a3));
        *(uint2*)(gG2lo + o) = make_uint2(pack_lo2(a0, a1), pack_lo2(a2, a3));
    }
}

// ---------------- per-graph counts + size features ----------------
__global__ void counts_kernel() {
    __shared__ float sn[NG], se[NG];
    if (threadIdx.x < NG) { sn[threadIdx.x] = 0.f; se[threadIdx.x] = 0.f; }
    __syncthreads();
    int stride = gridDim.x * blockDim.x;
    int tid = blockIdx.x * blockDim.x + threadIdx.x;
    for (int i = tid; i < NN; i += stride) atomicAdd(&sn[g_batch[i]], 1.f);
    for (int i = tid; i < NE; i += stride) atomicAdd(&se[g_batch[g_src[i]]], 1.f);
    __syncthreads();
    if (threadIdx.x < NG) {
        atomicAdd(&g_ncnt[threadIdx.x], sn[threadIdx.x]);
        atomicAdd(&g_ecnt[threadIdx.x], se[threadIdx.x]);
    }
}

__global__ void sf_kernel() {
    int stride = gridDim.x * blockDim.x;
    for (int i = blockIdx.x * blockDim.x + threadIdx.x; i < NN; i += stride) {
        int b = g_batch[i];
        g_sf[2*i + 0] = log1pf(g_ncnt[b]);
        g_sf[2*i + 1] = log1pf(g_ecnt[b]);
    }
}

// ---------------- weight preps ----------------
__global__ void wprep_kernel(const float* __restrict__ Ws0, const float* __restrict__ Wn0,
                             const float* __restrict__ Ws1, const float* __restrict__ Wn1) {
    int stride = gridDim.x * blockDim.x;
    const int TOT = 2*NEXP*HD*K2;
    for (int i = blockIdx.x * blockDim.x + threadIdx.x; i < TOT; i += stride) {
        int k = i & 511;
        int n = (i >> 9) & 255;
        int e = (i >> 17) & 7;
        int l = i >> 20;
        const float* Wsrc = (l == 0) ? (k < 256 ? Ws0 : Wn0) : (k < 256 ? Ws1 : Wn1);
        int kk = k & 255;
        g_w16[i] = __float2half_rn(Wsrc[((size_t)e*256 + kk)*256 + n]);
    }
}

__global__ void wr1prep_kernel(const float* __restrict__ Wr1) {
    int stride = gridDim.x * blockDim.x;
    for (int i = blockIdx.x * blockDim.x + threadIdx.x; i < HD*HD; i += stride) {
        int k = i & 255, n = i >> 8;
        split_store(g_wr1hi + (size_t)n*HD + k, g_wr1lo + (size_t)n*HD + k,
                    Wr1[(size_t)k*HD + n]);
    }
}

// ---------------- tensor-core router: split-fp16 3-term + in-kernel argmax ----------
#define R2_STG 49152          /* Ahi 8K | Alo 8K | Bhi 16K | Blo 16K */
#define R2_OFF_LGP  98304
#define R2_OFF_WR2 102400
#define R2_OFF_BIAS 110592
#define R2_OFF_W2A 111616
#define R2_OFF_W2B 112640
#define R2_DSMEM  113664

__device__ __forceinline__ void issue_loads_r(uint32_t sb, int stage, int kt, int mbase, int t) {
    uint32_t stg = sb + stage*R2_STG;
    #pragma unroll
    for (int q = 0; q < 2; q++) {     // A hi+lo: 1024 x 16B
        int lin = q*512 + t;
        int split = lin >> 9;
        int rem = lin & 511;
        int row = rem >> 2, ch = rem & 3;
        int node = mbase + row; if (node >= NN) node = NN - 1;
        const __half* src = (split ? gA1lo : gA1hi) + (size_t)node*K2 + kt*32 + ch*8;
        CP16(stg + split*8192 + sw64(row, ch), src);
    }
    #pragma unroll
    for (int q = 0; q < 4; q++) {     // B hi+lo: 2048 x 16B
        int lin = q*512 + t;
        int split = lin >> 10;
        int rem = lin & 1023;
        int n = rem >> 2, ch = rem & 3;
        const __half* src = (split ? g_wr1lo : g_wr1hi) + (size_t)n*HD + kt*32 + ch*8;
        CP16(stg + 16384 + split*16384 + sw64(n, ch), src);
    }
    CP_COMMIT();
}

__device__ __forceinline__ void mma_all4(float acc[4][4][4], uint32_t aF[4][4], uint32_t bF[2][4]) {
    #pragma unroll
    for (int mf = 0; mf < 4; mf++)
        #pragma unroll
        for (int nf = 0; nf < 4; nf++)
            mma16816(acc[mf][nf], aF[mf], bF[nf >> 1][(nf & 1)*2 + 0], bF[nf >> 1][(nf & 1)*2 + 1]);
}

__global__ void __launch_bounds__(512, 1) router_mma_kernel(
    const float* __restrict__ Wr1, const float* __restrict__ br1,
    const float* __restrict__ Wr2, const float* __restrict__ br2) {
    extern __shared__ char smem[];
    uint32_t sb = smem_u32(smem);
    int t = threadIdx.x;
    float* lgpS  = (float*)(smem + R2_OFF_LGP);    // [128][8]
    float* Wr2s  = (float*)(smem + R2_OFF_WR2);    // [256][8]
    float* biasS = (float*)(smem + R2_OFF_BIAS);
    float* w2aS  = (float*)(smem + R2_OFF_W2A);
    float* w2bS  = (float*)(smem + R2_OFF_W2B);
    int mbase = blockIdx.x * 128;

    issue_loads_r(sb, 0, 0, mbase, t);
    issue_loads_r(sb, 1, 1, mbase, t);

    if (t < 256) {
        biasS[t] = br1[t];
        w2aS[t] = Wr1[256*HD + t];
        w2bS[t] = Wr1[257*HD + t];
    }
    for (int i = t; i < 256*8; i += 512) Wr2s[i] = Wr2[i];
    for (int i = t; i < 128*8; i += 512) lgpS[i] = 0.f;

    float acc[4][4][4];
    #pragma unroll
    for (int mf = 0; mf < 4; mf++)
        #pragma unroll
        for (int nf = 0; nf < 4; nf++)
            #pragma unroll
            for (int c = 0; c < 4; c++) acc[mf][nf][c] = 0.f;

    int lane = t & 31, wid = t >> 5;
    int m0 = (wid >> 3) * 64;
    int n0 = (wid & 7) * 32;

    for (int kt = 0; kt < 8; kt++) {
        CP_WAIT1();
        __syncthreads();
        uint32_t stg = sb + (kt & 1)*R2_STG;
        #pragma unroll
        for (int k16 = 0; k16 < 2; k16++) {
            uint32_t aF[4][4], bF[2][4];
            int akk = k16*16 + (lane >> 4)*8;
            int arow = lane & 15;
            int bg = lane >> 3, brr = lane & 7;
            int bkk = k16*16 + (bg & 1)*8;
            #pragma unroll
            for (int nf2 = 0; nf2 < 2; nf2++) {
                int row = n0 + nf2*16 + ((bg >> 1) & 1)*8 + brr;
                LDSM4(bF[nf2][0], bF[nf2][1], bF[nf2][2], bF[nf2][3],
                      stg + 16384 + sw64(row, bkk >> 3));
            }
            #pragma unroll
            for (int mf = 0; mf < 4; mf++) {
                int row = m0 + mf*16 + arow;
                LDSM4(aF[mf][0], aF[mf][1], aF[mf][2], aF[mf][3], stg + sw64(row, akk >> 3));
            }
            mma_all4(acc, aF, bF);                       // Ahi * Bhi
            #pragma unroll
            for (int mf = 0; mf < 4; mf++) {
                int row = m0 + mf*16 + arow;
                LDSM4(aF[mf][0], aF[mf][1], aF[mf][2], aF[mf][3], stg + 8192 + sw64(row, akk >> 3));
            }
            mma_all4(acc, aF, bF);                       // Alo * Bhi
            #pragma unroll
            for (int nf2 = 0; nf2 < 2; nf2++) {
                int row = n0 + nf2*16 + ((bg >> 1) & 1)*8 + brr;
                LDSM4(bF[nf2][0], bF[nf2][1], bF[nf2][2], bF[nf2][3],
                      stg + 32768 + sw64(row, bkk >> 3));
            }
            #pragma unroll
            for (int mf = 0; mf < 4; mf++) {
                int row = m0 + mf*16 + arow;
                LDSM4(aF[mf][0], aF[mf][1], aF[mf][2], aF[mf][3], stg + sw64(row, akk >> 3));
            }
            mma_all4(acc, aF, bF);                       // Ahi * Blo
        }
        __syncthreads();
        if (kt + 2 < 8) issue_loads_r(sb, kt & 1, kt + 2, mbase, t);
        else CP_COMMIT();
    }

    // epilogue: relu'd r -> partial logits -> smem reduction
    #pragma unroll
    for (int mf = 0; mf < 4; mf++)
        #pragma unroll
        for (int p = 0; p < 2; p++) {
            int rloc = m0 + mf*16 + (lane >> 2) + p*8;
            int node = mbase + rloc;
            float sf0 = 0.f, sf1 = 0.f;
            if (node < NN) { sf0 = g_sf[2*node]; sf1 = g_sf[2*node + 1]; }
            float lp[NEXP];
            #pragma unroll
            for (int e = 0; e < NEXP; e++) lp[e] = 0.f;
            #pragma unroll
            for (int nf = 0; nf < 4; nf++)
                #pragma unroll
                for (int q = 0; q < 2; q++) {
                    int col = n0 + nf*8 + (lane & 3)*2 + q;
                    float r = acc[mf][nf][p*2+q] + sf0*w2aS[col] + sf1*w2bS[col] + biasS[col];
                    r = fmaxf(r, 0.f);
                    const float* wr = Wr2s + col*8;
                    #pragma unroll
                    for (int e = 0; e < NEXP; e++) lp[e] += r * wr[e];
                }
            #pragma unroll
            for (int off = 1; off < 4; off <<= 1)
                #pragma unroll
                for (int e = 0; e < NEXP; e++) lp[e] += __shfl_xor_sync(0xFFFFFFFFu, lp[e], off);
            if ((lane & 3) == 0 && node < NN) {
                #pragma unroll
                for (int e = 0; e < NEXP; e++) atomicAdd(&lgpS[rloc*8 + e], lp[e]);
            }
        }
    __syncthreads();

    if (t < 128) {
        int node = mbase + t;
        if (node < NN) {
            float v0 = lgpS[t*8 + 0] + br2[0];
            int best = 0; float bv = v0, second = -1e30f;
            #pragma unroll
            for (int e = 1; e < NEXP; e++) {
                float v = lgpS[t*8 + e] + br2[e];
                if (v > bv) { second = bv; bv = v; best = e; }
                else if (v > second) second = v;
            }
            g_idx[node] = best;
            if (bv - second < 1e-3f * fmaxf(fabsf(bv), 1.f)) {
                int pos = atomicAdd(&g_fixn, 1);
                if (pos < FIXCAP) g_fixlist[pos] = node;
            }
        }
    }
}

// ---------------- exact fp32 fixup for near-tie nodes ----------------
__global__ void fixup_kernel(const float* __restrict__ Wr1, const float* __restrict__ br1,
                             const float* __restrict__ Wr2, const float* __restrict__ br2) {
    int nwarps = (gridDim.x * blockDim.x) >> 5;
    int w = (blockIdx.x * blockDim.x + threadIdx.x) >> 5;
    int lane = threadIdx.x & 31;
    int n = g_fixn; if (n > FIXCAP) n = FIXCAP;
    for (int f = w; f < n; f += nwarps) {
        int node = g_fixlist[f];
        float hreg[8];
        #pragma unroll
        for (int j = 0; j < 8; j++) hreg[j] = g_h[(size_t)node*HD + j*32 + lane];
        float r[8];
        #pragma unroll
        for (int j = 0; j < 8; j++) r[j] = 0.f;
        for (int k = 0; k < 256; k++) {
            float hk = __shfl_sync(0xFFFFFFFFu, hreg[k >> 5], k & 31);
            const float* wrow = Wr1 + (size_t)k*HD + lane;
            #pragma unroll
            for (int j = 0; j < 8; j++) r[j] += hk * wrow[j*32];
        }
        float sf0 = g_sf[2*node], sf1 = g_sf[2*node + 1];
        float lp[NEXP];
        #pragma unroll
        for (int e = 0; e < NEXP; e++) lp[e] = 0.f;
        #pragma unroll
        for (int j = 0; j < 8; j++) {
            int col = j*32 + lane;
            float rv = r[j] + sf0*Wr1[256*HD + col] + sf1*Wr1[257*HD + col] + br1[col];
            rv = fmaxf(rv, 0.f);
            #pragma unroll
            for (int e = 0; e < NEXP; e++) lp[e] += rv * Wr2[col*8 + e];
        }
        #pragma unroll
        for (int off = 16; off > 0; off >>= 1)
            #pragma unroll
            for (int e = 0; e < NEXP; e++) lp[e] += __shfl_xor_sync(0xFFFFFFFFu, lp[e], off);
        if (lane == 0) {
            int best = 0; float bv = lp[0] + br2[0];
            #pragma unroll
            for (int e = 1; e < NEXP; e++) {
                float v = lp[e] + br2[e];
                if (v > bv) { bv = v; best = e; }
            }
            g_idx[node] = best;
        }
    }
}

// ---------------- bucket nodes by expert (padded to 128) ----------------
__global__ void bucket_count_kernel() {
    __shared__ int sc[NEXP];
    if (threadIdx.x < NEXP) sc[threadIdx.x] = 0;
    __syncthreads();
    int stride = gridDim.x * blockDim.x;
    for (int i = blockIdx.x * blockDim.x + threadIdx.x; i < NN; i += stride)
        atomicAdd(&sc[g_idx[i]], 1);
    __syncthreads();
    if (threadIdx.x < NEXP) atomicAdd(&g_cnt[threadIdx.x], sc[threadIdx.x]);
}

__global__ void bucket_scan_kernel() {
    if (threadIdx.x == 0 && blockIdx.x == 0) {
        int off = 0;
        for (int e = 0; e < NEXP; e++) {
            g_poff[e] = off;
            g_cursor[e] = off;
            off += ((g_cnt[e] + 127) / 128) * 128;
        }
        g_poff[NEXP] = off;
    }
}

__global__ void bucket_scatter_kernel() {
    int stride = gridDim.x * blockDim.x;
    for (int i = blockIdx.x * blockDim.x + threadIdx.x; i < NN; i += stride) {
        int pos = atomicAdd(&g_cursor[g_idx[i]], 1);
        g_list[pos] = i;
    }
}

// ---------------- fp16 2-term tensor-core GEMM, 512 threads ----------------------
#define STGSZ 32768          /* per-stage: Ahi 8K | Alo 8K | B 16K */
#define NSTG 3
#define OFF_ROWS 98304
#define OFF_BIAS 98816
#define DSMEM    99840

__device__ __forceinline__ void issue_loads(uint32_t sb, int stage, int kt, int layer, int e,
                                            const int* rowsS, int t) {
    uint32_t stg = sb + stage*STGSZ;
    #pragma unroll
    for (int q = 0; q < 2; q++) {     // A hi+lo: 1024 x 16B over 512 threads
        int lin = q*512 + t;
        int split = lin >> 9;
        int rem = lin & 511;
        int row = rem >> 2, ch = rem & 3;
        int node = rowsS[row]; if (node < 0) node = 0;
        const __half* src;
        if (layer == 0) {
            src = (split ? gA1lo : gA1hi) + (size_t)node*K2 + kt*32 + ch*8;
        } else {
            int k0 = kt*32;
            if (k0 < 256) src = (split ? gZlo : gZhi) + ((size_t)e*NN + node)*HD + k0 + ch*8;
            else          src = (split ? gG2lo : gG2hi) + (size_t)node*HD + (k0 - 256) + ch*8;
        }
        CP16(stg + split*8192 + sw64(row, ch), src);
    }
    #pragma unroll
    for (int q = 0; q < 2; q++) {     // B: 1024 x 16B over 512 threads
        int lin = q*512 + t;
        int n = lin >> 2, ch = lin & 3;
        const __half* src = g_w16
            + ((size_t)((layer*NEXP + e)*256 + n))*K2 + kt*32 + ch*8;
        CP16(stg + 16384 + sw64(n, ch), src);
    }
    CP_COMMIT();
}

__global__ void __launch_bounds__(512, 1) moe_mma_kernel(
    const float* __restrict__ bias_base, int layer,
    float* __restrict__ outL2) {
    extern __shared__ char smem[];
    uint32_t sb = smem_u32(smem);
    int t = threadIdx.x;
    int* rowsS = (int*)(smem + OFF_ROWS);
    float* biasS = (float*)(smem + OFF_BIAS);

    int e;
    if (layer == 0) {
        e = blockIdx.x & 7;                 // expert-inner: A tile shared in L2
        int mtile = blockIdx.x >> 3;
        if (t < 128) {
            int m = mtile * 128 + t;
            rowsS[t] = (m < NN) ? m : -1;
        }
    } else {
        int b = blockIdx.x;
        if (b * 128 >= g_poff[NEXP]) return;
        int ee = 0;
        while (b * 128 >= g_poff[ee + 1]) ee++;
        e = ee;
        if (t < 128) rowsS[t] = g_list[b * 128 + t];
    }
    if (t < 256) biasS[t] = bias_base[e*HD + t];
    __syncthreads();

    float acc[4][4][4];
    #pragma unroll
    for (int mf = 0; mf < 4; mf++)
        #pragma unroll
        for (int nf = 0; nf < 4; nf++)
            #pragma unroll
            for (int c = 0; c < 4; c++) acc[mf][nf][c] = 0.f;

    int lane = t & 31, wid = t >> 5;
    int m0 = (wid >> 3) * 64;      // 2 m-warps
    int n0 = (wid & 7) * 32;       // 8 n-warps

    issue_loads(sb, 0, 0, layer, e, rowsS, t);
    issue_loads(sb, 1, 1, layer, e, rowsS, t);
    issue_loads(sb, 2, 2, layer, e, rowsS, t);

    for (int kt = 0; kt < 16; kt++) {
        CP_WAIT2();
        __syncthreads();
        uint32_t stg = sb + (kt % NSTG)*STGSZ;
        #pragma unroll
        for (int k16 = 0; k16 < 2; k16++) {
            uint32_t aF[4][4], bF[2][4];
            int akk = k16*16 + (lane >> 4)*8;
            int arow = lane & 15;
            int bg = lane >> 3, brr = lane & 7;
            int bkk = k16*16 + (bg & 1)*8;
            #pragma unroll
            for (int nf2 = 0; nf2 < 2; nf2++) {
                int row = n0 + nf2*16 + ((bg >> 1) & 1)*8 + brr;
                LDSM4(bF[nf2][0], bF[nf2][1], bF[nf2][2], bF[nf2][3],
                      stg + 16384 + sw64(row, bkk >> 3));
            }
            #pragma unroll
            for (int mf = 0; mf < 4; mf++) {
                int row = m0 + mf*16 + arow;
                LDSM4(aF[mf][0], aF[mf][1], aF[mf][2], aF[mf][3], stg + sw64(row, akk >> 3));
            }
            mma_all4(acc, aF, bF);                       // Ahi * B
            #pragma unroll
            for (int mf = 0; mf < 4; mf++) {
                int row = m0 + mf*16 + arow;
                LDSM4(aF[mf][0], aF[mf][1], aF[mf][2], aF[mf][3], stg + 8192 + sw64(row, akk >> 3));
            }
            mma_all4(acc, aF, bF);                       // Alo * B
        }
        __syncthreads();
        if (kt + NSTG < 16) issue_loads(sb, kt % NSTG, kt + NSTG, layer, e, rowsS, t);
        else CP_COMMIT();
    }

    // ---------------- epilogue ----------------
    if (layer == 0) {
        #pragma unroll
        for (int mf = 0; mf < 4; mf++)
            #pragma unroll
            for (int p = 0; p < 2; p++) {
                int row = m0 + mf*16 + (lane >> 2) + p*8;
                int node = rowsS[row];
                if (node < 0) continue;
                size_t base = ((size_t)e*NN + node)*HD;
                #pragma unroll
                for (int nf = 0; nf < 4; nf++) {
                    int col = n0 + nf*8 + (lane & 3)*2;
                    float z0 = fmaxf(acc[mf][nf][p*2+0] + biasS[col],     0.f);
                    float z1 = fmaxf(acc[mf][nf][p*2+1] + biasS[col + 1], 0.f);
                    *(uint32_t*)(gZhi + base + col) = pack2(z0, z1);
                    *(uint32_t*)(gZlo + base + col) = pack_lo2(z0, z1);
                }
            }
    } else {
        #pragma unroll
        for (int mf = 0; mf < 4; mf++)
            #pragma unroll
            for (int p = 0; p < 2; p++) {
                int row = m0 + mf*16 + (lane >> 2) + p*8;
                int node = rowsS[row];
                if (node < 0) continue;
                float* orow = outL2 + (size_t)node*HD;
                #pragma unroll
                for (int nf = 0; nf < 4; nf++) {
                    int col = n0 + nf*8 + (lane & 3)*2;
                    float o0 = acc[mf][nf][p*2+0] + biasS[col];
                    float o1 = acc[mf][nf][p*2+1] + biasS[col + 1];
                    *(float2*)(orow + col) = make_float2(o0, o1);
                }
            }
    }
}

// ---------------- launch: R14 schedule + fast 3-phase scan ----------------
extern "C" void kernel_launch(void* const* d_in, const int* in_sizes, int n_in,
                              void* d_out, int out_size) {
    (void)in_sizes; (void)n_in; (void)out_size;
    const float* x     = (const float*)d_in[0];
    const void*  ei    = d_in[1];
    const void*  batch = d_in[2];
    const float* W_enc = (const float*)d_in[3];
    const float* b_enc = (const float*)d_in[4];
    const float* Wr1   = (const float*)d_in[5];
    const float* br1   = (const float*)d_in[6];
    const float* Wr2   = (const float*)d_in[7];
    const float* br2   = (const float*)d_in[8];
    const float* Ws0   = (const float*)d_in[9];
    const float* Wn0   = (const float*)d_in[10];
    const float* b0    = (const float*)d_in[11];
    const float* Ws1   = (const float*)d_in[12];
    const float* Wn1   = (const float*)d_in[13];
    const float* b1    = (const float*)d_in[14];
    float* out = (float*)d_out;

    static cudaStream_t s1 = nullptr;
    static cudaEvent_t evStart, evEnc, evW, evB;
    if (!s1) {
        cudaStreamCreateWithFlags(&s1, cudaStreamNonBlocking);
        cudaEventCreateWithFlags(&evStart, cudaEventDisableTiming);
        cudaEventCreateWithFlags(&evEnc,   cudaEventDisableTiming);
        cudaEventCreateWithFlags(&evW,     cudaEventDisableTiming);
        cudaEventCreateWithFlags(&evB,     cudaEventDisableTiming);
        cudaFuncSetAttribute(moe_mma_kernel,
                             cudaFuncAttributeMaxDynamicSharedMemorySize, DSMEM);
        cudaFuncSetAttribute(router_mma_kernel,
                             cudaFuncAttributeMaxDynamicSharedMemorySize, R2_DSMEM);
    }

    // fork: side stream does weight prep immediately
    cudaEventRecord(evStart, 0);
    cudaStreamWaitEvent(s1, evStart, 0);
    wprep_kernel<<<2048, 256, 0, s1>>>(Ws0, Wn0, Ws1, Wn1);
    cudaEventRecord(evW, s1);
    wr1prep_kernel<<<256, 256, 0, s1>>>(Wr1);

    // main stream: init -> convert(+hist) -> encoder
    detect_kernel<<<1, 32>>>((const unsigned int*)ei);
    init_kernel<<<512, 256>>>();
    convert_kernel<<<2048, 256>>>(ei, batch);
    encoder_kernel<<<2048, 256>>>(x, W_enc, b_enc);
    cudaEventRecord(evEnc, 0);

    // side stream: tensor router chain (hidden under CSR + aggh + GEMM1)
    cudaStreamWaitEvent(s1, evEnc, 0);
    counts_kernel<<<512, 256, 0, s1>>>();
    sf_kernel<<<256, 256, 0, s1>>>();
    router_mma_kernel<<<MT, 512, R2_DSMEM, s1>>>(Wr1, br1, Wr2, br2);
    fixup_kernel<<<64, 256, 0, s1>>>(Wr1, br1, Wr2, br2);
    bucket_count_kernel<<<512, 256, 0, s1>>>();
    bucket_scan_kernel<<<1, 1, 0, s1>>>();
    bucket_scatter_kernel<<<256, 256, 0, s1>>>();
    cudaEventRecord(evB, s1);

    // main stream: fast CSR + aggh (overlaps router chain)
    scan_part_kernel<<<NBS, 512>>>();
    scan_top_kernel<<<1, 128>>>();
    scan_apply_kernel<<<NBS, 512>>>();
    scatter_kernel<<<1024, 256>>>();
    aggh_kernel<<<6250, 256>>>();

    // layer-1: single launch, expert-inner block order (8x A reuse in L2)
    cudaStreamWaitEvent(0, evW, 0);
    moe_mma_kernel<<<MT*NEXP, 512, DSMEM>>>(b0, 0, nullptr);

    // aggregation over all buckets at once, then layer-2 single launch
    cudaStreamWaitEvent(0, evB, 0);
    aggz_kernel<<<6250, 256>>>();
    moe_mma_kernel<<<400, 512, DSMEM>>>(b1, 1, out);
}

// round 17
// speedup vs baseline: 1.1747x; 1.1280x over previous
#include <cuda_runtime.h>
#include <cuda_fp16.h>
#include <math.h>
#include <stdint.h>

#define NN 50000
#define NE 800000
#define HD 256
#define K2 512
#define NEXP 8
#define NG 64
#define LIST_SZ (NN + NEXP*128)
#define MT 391           /* ceil(50000/128) */
#define FIXCAP 16384
#define NBS 98           /* ceil(50000/512) scan blocks */

// ---------------- scratch (static device globals; no allocation) ----------------
static __device__ float g_h[(size_t)NN*HD];
static __device__ float g_sf[(size_t)NN*2];
static __device__ int   g_src[NE];
static __device__ int   g_dst[NE];
static __device__ int   g_batch[NN];
static __device__ float g_ncnt[NG];
static __device__ float g_ecnt[NG];
static __device__ int   g_idx[NN];
static __device__ int   g_cnt[NEXP];
static __device__ int   g_cursor[NEXP];
static __device__ int   g_poff[NEXP+1];
static __device__ int   g_list[LIST_SZ];
static __device__ int   g_is64;
static __device__ int   g_deg[NN];
static __device__ int   g_rowptr[NN+1];
static __device__ int   g_wcur[NN];
static __device__ int   g_csrc[NE];
static __device__ int   g_fixn;
static __device__ int   g_fixlist[FIXCAP];
static __device__ int   g_bsum[NBS];
static __device__ int   g_boff[NBS];
static __device__ __half g_w16[(size_t)2*NEXP*HD*K2];   // [layer][expert][n][k] K-major fp16
static __device__ __half g_wr1hi[(size_t)HD*HD];        // router Wr1 [n][k] K-major split
static __device__ __half g_wr1lo[(size_t)HD*HD];
static __device__ __half gA1hi[(size_t)NN*K2];          // [node][512] = [h|aggh] hi
static __device__ __half gA1lo[(size_t)NN*K2];          // lo
static __device__ __half gZhi[(size_t)NEXP*NN*HD];      // [e][node][256] hi
static __device__ __half gZlo[(size_t)NEXP*NN*HD];      // lo
static __device__ __half gG2hi[(size_t)NN*HD];          // agg2 hi
static __device__ __half gG2lo[(size_t)NN*HD];          // agg2 lo

// ================= PTX helpers (arch-agnostic: sm_80+ only) =================
__device__ __forceinline__ uint32_t smem_u32(const void* p) {
    uint32_t a;
    asm("{ .reg .u64 t; cvta.to.shared.u64 t, %1; cvt.u32.u64 %0, t; }" : "=r"(a) : "l"(p));
    return a;
}
#define CP16(dst, src) \
    asm volatile("cp.async.cg.shared.global [%0], [%1], 16;" :: "r"(dst), "l"(src) : "memory")
#define CP_COMMIT()  asm volatile("cp.async.commit_group;" ::: "memory")
#define CP_WAIT1()   asm volatile("cp.async.wait_group 1;" ::: "memory")
#define CP_WAIT2()   asm volatile("cp.async.wait_group 2;" ::: "memory")

#define LDSM4(r0, r1, r2, r3, addr) \
    asm volatile("ldmatrix.sync.aligned.m8n8.x4.shared.b16 {%0,%1,%2,%3}, [%4];" \
                 : "=r"(r0), "=r"(r1), "=r"(r2), "=r"(r3) : "r"(addr))

__device__ __forceinline__ void mma16816(float* c, const uint32_t* a, uint32_t b0, uint32_t b1) {
    asm volatile(
        "mma.sync.aligned.m16n8k16.row.col.f32.f16.f16.f32 "
        "{%0,%1,%2,%3}, {%4,%5,%6,%7}, {%8,%9}, {%0,%1,%2,%3};"
        : "+f"(c[0]), "+f"(c[1]), "+f"(c[2]), "+f"(c[3])
        : "r"(a[0]), "r"(a[1]), "r"(a[2]), "r"(a[3]), "r"(b0), "r"(b1));
}

// 64B-row swizzle: element (row, 16B-chunk ch) -> row*64 + (ch ^ ((row>>1)&3))*16
__device__ __forceinline__ uint32_t sw64(int row, int ch) {
    return (uint32_t)row*64u + (uint32_t)((ch ^ ((row >> 1) & 3)) << 4);
}

__device__ __forceinline__ uint32_t pack2(float x, float y) {
    return ((uint32_t)__half_as_ushort(__float2half_rn(y)) << 16)
         | __half_as_ushort(__float2half_rn(x));
}
__device__ __forceinline__ uint32_t pack_lo2(float x, float y) {
    float rx = x - __half2float(__float2half_rn(x));
    float ry = y - __half2float(__float2half_rn(y));
    return ((uint32_t)__half_as_ushort(__float2half_rn(ry)) << 16)
         | __half_as_ushort(__float2half_rn(rx));
}
__device__ __forceinline__ void split_store(__half* hi, __half* lo, float v) {
    __half h = __float2half_rn(v);
    *hi = h;
    *lo = __float2half_rn(v - __half2float(h));
}

// ---------------- dtype detect + convert (+ fused degree histogram) ----------------
__global__ void detect_kernel(const unsigned int* ei) {
    if (threadIdx.x == 0 && blockIdx.x == 0) {
        int flag = 1;
        for (int j = 0; j < 64; j++)
            if (ei[2*j + 1] != 0u) { flag = 0; break; }
        g_is64 = flag;
    }
}

__global__ void convert_kernel(const void* ei, const void* batch) {
    int is64 = g_is64;
    int stride = gridDim.x * blockDim.x;
    int tid = blockIdx.x * blockDim.x + threadIdx.x;
    if (is64) {
        const long long* e64 = (const long long*)ei;
        const long long* b64 = (const long long*)batch;
        for (int i = tid; i < NE; i += stride) {
            int d = (int)e64[NE + i];
            g_src[i] = (int)e64[i];
            g_dst[i] = d;
            atomicAdd(&g_deg[d], 1);
        }
        for (int i = tid; i < NN; i += stride) g_batch[i] = (int)b64[i];
    } else {
        const int* e32 = (const int*)ei;
        const int* b32 = (const int*)batch;
        for (int i = tid; i < NE; i += stride) {
            int d = e32[NE + i];
            g_src[i] = e32[i];
            g_dst[i] = d;
            atomicAdd(&g_deg[d], 1);
        }
        for (int i = tid; i < NN; i += stride) g_batch[i] = b32[i];
    }
}

// ---------------- init ----------------
__global__ void init_kernel() {
    int stride = gridDim.x * blockDim.x;
    int tid = blockIdx.x * blockDim.x + threadIdx.x;
    for (int i = tid; i < LIST_SZ; i += stride) g_list[i] = -1;
    for (int i = tid; i < NN; i += stride) g_deg[i] = 0;
    if (tid < NG) { g_ncnt[tid] = 0.f; g_ecnt[tid] = 0.f; }
    if (tid < NEXP) g_cnt[tid] = 0;
    if (tid == 0) g_fixn = 0;
}

// ---------------- encoder: h + split write of A1 h-half ----------------
__global__ void encoder_kernel(const float* __restrict__ x,
                               const float* __restrict__ W,
                               const float* __restrict__ b) {
    __shared__ float Ws[6*HD];
    for (int i = threadIdx.x; i < 6*HD; i += blockDim.x) Ws[i] = W[i];
    __syncthreads();
    int n = threadIdx.x;
    float bn = b[n];
    for (int row = blockIdx.x; row < NN; row += gridDim.x) {
        float x0 = x[row*6+0], x1 = x[row*6+1], x2 = x[row*6+2];
        float x3 = x[row*6+3], x4 = x[row*6+4], x5 = x[row*6+5];
        float s = bn;
        s += x0 * Ws[0*HD+n]; s += x1 * Ws[1*HD+n]; s += x2 * Ws[2*HD+n];
        s += x3 * Ws[3*HD+n]; s += x4 * Ws[4*HD+n]; s += x5 * Ws[5*HD+n];
        float h = fmaxf(s, 0.f);
        g_h[(size_t)row*HD + n] = h;
        split_store(gA1hi + (size_t)row*K2 + n, gA1lo + (size_t)row*K2 + n, h);
    }
}

// ---------------- CSR build: 3-phase parallel scan ----------------
__global__ void scan_part_kernel() {       // NBS blocks x 512
    __shared__ int sh[512];
    int t = threadIdx.x;
    int n = blockIdx.x * 512 + t;
    int v = (n < NN) ? g_deg[n] : 0;
    sh[t] = v;
    __syncthreads();
    #pragma unroll
    for (int off = 1; off < 512; off <<= 1) {
        int y = (t >= off) ? sh[t - off] : 0;
        __syncthreads();
        sh[t] += y;
        __syncthreads();
    }
    if (n < NN) g_rowptr[n] = sh[t] - v;   // local exclusive
    if (t == 511) g_bsum[blockIdx.x] = sh[511];
}

__global__ void scan_top_kernel() {        // 1 block x 128
    __shared__ int sh[128];
    int t = threadIdx.x;
    int v = (t < NBS) ? g_bsum[t] : 0;
    sh[t] = v;
    __syncthreads();
    #pragma unroll
    for (int off = 1; off < 128; off <<= 1) {
        int y = (t >= off) ? sh[t - off] : 0;
        __syncthreads();
        sh[t] += y;
        __syncthreads();
    }
    if (t < NBS) g_boff[t] = sh[t] - v;
}

__global__ void scan_apply_kernel() {      // NBS blocks x 512
    int n = blockIdx.x * 512 + threadIdx.x;
    if (n < NN) {
        int r = g_rowptr[n] + g_boff[blockIdx.x];
        g_rowptr[n] = r;
        g_wcur[n] = r;
    }
    if (n == 0) g_rowptr[NN] = NE;
}

__global__ void scatter_kernel() {
    int stride = gridDim.x * blockDim.x;
    for (int i = blockIdx.x * blockDim.x + threadIdx.x; i < NE; i += stride) {
        int d = g_dst[i];
        int pos = atomicAdd(&g_wcur[d], 1);
        g_csrc[pos] = g_src[i];
    }
}

// ---------------- aggh: A@h (fp16-hi gathers, deg-averaged quant) -> split write ----
__global__ void aggh_kernel() {
    int nwarps = (gridDim.x * blockDim.x) >> 5;
    int w = (blockIdx.x * blockDim.x + threadIdx.x) >> 5;
    int lane = threadIdx.x & 31;
    for (int u = w; u < 2*NN; u += nwarps) {
        int node = u >> 1;
        int c0 = (u & 1) * 128 + lane * 4;
        float a0 = 0.f, a1 = 0.f, a2 = 0.f, a3 = 0.f;
        int b = g_rowptr[node], en = g_rowptr[node+1];
        for (int p = b; p < en; p++) {
            uint2 vh = *(const uint2*)(gA1hi + (size_t)g_csrc[p]*K2 + c0);
            float2 h0 = __half22float2(*(__half2*)&vh.x);
            float2 h1 = __half22float2(*(__half2*)&vh.y);
            a0 += h0.x; a1 += h0.y; a2 += h1.x; a3 += h1.y;
        }
        size_t o = (size_t)node*K2 + 256 + c0;
        *(uint2*)(gA1hi + o) = make_uint2(pack2(a0, a1), pack2(a2, a3));
        *(uint2*)(gA1lo + o) = make_uint2(pack_lo2(a0, a1), pack_lo2(a2, a3));
    }
}

// ---------------- aggz over expert range [e0,e1): hi-only gathers -> split agg2 -----
__global__ void aggz_kernel(int e0, int e1) {
    int nwarps = (gridDim.x * blockDim.x) >> 5;
    int w = (blockIdx.x * blockDim.x + threadIdx.x) >> 5;
    int lane = threadIdx.x & 31;
    int u0 = 2 * g_poff[e0], u1 = 2 * g_poff[e1];
    for (int u = u0 + w; u < u1; u += nwarps) {
        int node = g_list[u >> 1];
        if (node < 0) continue;
        int c0 = (u & 1) * 128 + lane * 4;
        const __half* zh = gZhi + (size_t)g_idx[node]*NN*HD;
        float a0 = 0.f, a1 = 0.f, a2 = 0.f, a3 = 0.f;
        int b = g_rowptr[node], en = g_rowptr[node+1];
        for (int p = b; p < en; p++) {
            uint2 vh = *(const uint2*)(zh + (size_t)g_csrc[p]*HD + c0);
            float2 h0 = __half22float2(*(__half2*)&vh.x);
            float2 h1 = __half22float2(*(__half2*)&vh.y);
            a0 += h0.x; a1 += h0.y; a2 += h1.x; a3 += h1.y;
        }
        size_t o = (size_t)node*HD + c0;
        *(uint2*)(gG2hi + o) = make_uint2(pack2(a0, a1), pack2(a2, a3));
        *(uint2*)(gG2lo + o) = make_uint2(pack_lo2(a0, a1), pack_lo2(a2, a3));
    }
}

// ---------------- per-graph counts + size features ----------------
__global__ void counts_kernel() {
    __shared__ float sn[NG], se[NG];
    if (threadIdx.x < NG) { sn[threadIdx.x] = 0.f; se[threadIdx.x] = 0.f; }
    __syncthreads();
    int stride = gridDim.x * blockDim.x;
    int tid = blockIdx.x * blockDim.x + threadIdx.x;
    for (int i = tid; i < NN; i += stride) atomicAdd(&sn[g_batch[i]], 1.f);
    for (int i = tid; i < NE; i += stride) atomicAdd(&se[g_batch[g_src[i]]], 1.f);
    __syncthreads();
    if (threadIdx.x < NG) {
        atomicAdd(&g_ncnt[threadIdx.x], sn[threadIdx.x]);
        atomicAdd(&g_ecnt[threadIdx.x], se[threadIdx.x]);
    }
}

__global__ void sf_kernel() {
    int stride = gridDim.x * blockDim.x;
    for (int i = blockIdx.x * blockDim.x + threadIdx.x; i < NN; i += stride) {
        int b = g_batch[i];
        g_sf[2*i + 0] = log1pf(g_ncnt[b]);
        g_sf[2*i + 1] = log1pf(g_ecnt[b]);
    }
}

// ---------------- weight preps ----------------
__global__ void wprep_kernel(const float* __restrict__ Ws0, const float* __restrict__ Wn0,
                             const float* __restrict__ Ws1, const float* __restrict__ Wn1) {
    int stride = gridDim.x * blockDim.x;
    const int TOT = 2*NEXP*HD*K2;
    for (int i = blockIdx.x * blockDim.x + threadIdx.x; i < TOT; i += stride) {
        int k = i & 511;
        int n = (i >> 9) & 255;
        int e = (i >> 17) & 7;
        int l = i >> 20;
        const float* Wsrc = (l == 0) ? (k < 256 ? Ws0 : Wn0) : (k < 256 ? Ws1 : Wn1);
        int kk = k & 255;
        g_w16[i] = __float2half_rn(Wsrc[((size_t)e*256 + kk)*256 + n]);
    }
}

__global__ void wr1prep_kernel(const float* __restrict__ Wr1) {
    int stride = gridDim.x * blockDim.x;
    for (int i = blockIdx.x * blockDim.x + threadIdx.x; i < HD*HD; i += stride) {
        int k = i & 255, n = i >> 8;
        split_store(g_wr1hi + (size_t)n*HD + k, g_wr1lo + (size_t)n*HD + k,
                    Wr1[(size_t)k*HD + n]);
    }
}

// ---------------- tensor-core router: split-fp16 3-term + in-kernel argmax ----------
#define R2_STG 49152          /* Ahi 8K | Alo 8K | Bhi 16K | Blo 16K */
#define R2_OFF_LGP  98304
#define R2_OFF_WR2 102400
#define R2_OFF_BIAS 110592
#define R2_OFF_W2A 111616
#define R2_OFF_W2B 112640
#define R2_DSMEM  113664

__device__ __forceinline__ void issue_loads_r(uint32_t sb, int stage, int kt, int mbase, int t) {
    uint32_t stg = sb + stage*R2_STG;
    #pragma unroll
    for (int q = 0; q < 2; q++) {     // A hi+lo: 1024 x 16B
        int lin = q*512 + t;
        int split = lin >> 9;
        int rem = lin & 511;
        int row = rem >> 2, ch = rem & 3;
        int node = mbase + row; if (node >= NN) node = NN - 1;
        const __half* src = (split ? gA1lo : gA1hi) + (size_t)node*K2 + kt*32 + ch*8;
        CP16(stg + split*8192 + sw64(row, ch), src);
    }
    #pragma unroll
    for (int q = 0; q < 4; q++) {     // B hi+lo: 2048 x 16B
        int lin = q*512 + t;
        int split = lin >> 10;
        int rem = lin & 1023;
        int n = rem >> 2, ch = rem & 3;
        const __half* src = (split ? g_wr1lo : g_wr1hi) + (size_t)n*HD + kt*32 + ch*8;
        CP16(stg + 16384 + split*16384 + sw64(n, ch), src);
    }
    CP_COMMIT();
}

__device__ __forceinline__ void mma_all4(float acc[4][4][4], uint32_t aF[4][4], uint32_t bF[2][4]) {
    #pragma unroll
    for (int mf = 0; mf < 4; mf++)
        #pragma unroll
        for (int nf = 0; nf < 4; nf++)
            mma16816(acc[mf][nf], aF[mf], bF[nf >> 1][(nf & 1)*2 + 0], bF[nf >> 1][(nf & 1)*2 + 1]);
}

__global__ void __launch_bounds__(512, 1) router_mma_kernel(
    const float* __restrict__ Wr1, const float* __restrict__ br1,
    const float* __restrict__ Wr2, const float* __restrict__ br2) {
    extern __shared__ char smem[];
    uint32_t sb = smem_u32(smem);
    int t = threadIdx.x;
    float* lgpS  = (float*)(smem + R2_OFF_LGP);    // [128][8]
    float* Wr2s  = (float*)(smem + R2_OFF_WR2);    // [256][8]
    float* biasS = (float*)(smem + R2_OFF_BIAS);
    float* w2aS  = (float*)(smem + R2_OFF_W2A);
    float* w2bS  = (float*)(smem + R2_OFF_W2B);
    int mbase = blockIdx.x * 128;

    issue_loads_r(sb, 0, 0, mbase, t);
    issue_loads_r(sb, 1, 1, mbase, t);

    if (t < 256) {
        biasS[t] = br1[t];
        w2aS[t] = Wr1[256*HD + t];
        w2bS[t] = Wr1[257*HD + t];
    }
    for (int i = t; i < 256*8; i += 512) Wr2s[i] = Wr2[i];
    for (int i = t; i < 128*8; i += 512) lgpS[i] = 0.f;

    float acc[4][4][4];
    #pragma unroll
    for (int mf = 0; mf < 4; mf++)
        #pragma unroll
        for (int nf = 0; nf < 4; nf++)
            #pragma unroll
            for (int c = 0; c < 4; c++) acc[mf][nf][c] = 0.f;

    int lane = t & 31, wid = t >> 5;
    int m0 = (wid >> 3) * 64;
    int n0 = (wid & 7) * 32;

    for (int kt = 0; kt < 8; kt++) {
        CP_WAIT1();
        __syncthreads();
        uint32_t stg = sb + (kt & 1)*R2_STG;
        #pragma unroll
        for (int k16 = 0; k16 < 2; k16++) {
            uint32_t aF[4][4], bF[2][4];
            int akk = k16*16 + (lane >> 4)*8;
            int arow = lane & 15;
            int bg = lane >> 3, brr = lane & 7;
            int bkk = k16*16 + (bg & 1)*8;
            #pragma unroll
            for (int nf2 = 0; nf2 < 2; nf2++) {
                int row = n0 + nf2*16 + ((bg >> 1) & 1)*8 + brr;
                LDSM4(bF[nf2][0], bF[nf2][1], bF[nf2][2], bF[nf2][3],
                      stg + 16384 + sw64(row, bkk >> 3));
            }
            #pragma unroll
            for (int mf = 0; mf < 4; mf++) {
                int row = m0 + mf*16 + arow;
                LDSM4(aF[mf][0], aF[mf][1], aF[mf][2], aF[mf][3], stg + sw64(row, akk >> 3));
            }
            mma_all4(acc, aF, bF);                       // Ahi * Bhi
            #pragma unroll
            for (int mf = 0; mf < 4; mf++) {
                int row = m0 + mf*16 + arow;
                LDSM4(aF[mf][0], aF[mf][1], aF[mf][2], aF[mf][3], stg + 8192 + sw64(row, akk >> 3));
            }
            mma_all4(acc, aF, bF);                       // Alo * Bhi
            #pragma unroll
            for (int nf2 = 0; nf2 < 2; nf2++) {
                int row = n0 + nf2*16 + ((bg >> 1) & 1)*8 + brr;
                LDSM4(bF[nf2][0], bF[nf2][1], bF[nf2][2], bF[nf2][3],
                      stg + 32768 + sw64(row, bkk >> 3));
            }
            #pragma unroll
            for (int mf = 0; mf < 4; mf++) {
                int row = m0 + mf*16 + arow;
                LDSM4(aF[mf][0], aF[mf][1], aF[mf][2], aF[mf][3], stg + sw64(row, akk >> 3));
            }
            mma_all4(acc, aF, bF);                       // Ahi * Blo
        }
        __syncthreads();
        if (kt + 2 < 8) issue_loads_r(sb, kt & 1, kt + 2, mbase, t);
        else CP_COMMIT();
    }

    // epilogue: relu'd r -> partial logits -> smem reduction
    #pragma unroll
    for (int mf = 0; mf < 4; mf++)
        #pragma unroll
        for (int p = 0; p < 2; p++) {
            int rloc = m0 + mf*16 + (lane >> 2) + p*8;
            int node = mbase + rloc;
            float sf0 = 0.f, sf1 = 0.f;
            if (node < NN) { sf0 = g_sf[2*node]; sf1 = g_sf[2*node + 1]; }
            float lp[NEXP];
            #pragma unroll
            for (int e = 0; e < NEXP; e++) lp[e] = 0.f;
            #pragma unroll
            for (int nf = 0; nf < 4; nf++)
                #pragma unroll
                for (int q = 0; q < 2; q++) {
                    int col = n0 + nf*8 + (lane & 3)*2 + q;
                    float r = acc[mf][nf][p*2+q] + sf0*w2aS[col] + sf1*w2bS[col] + biasS[col];
                    r = fmaxf(r, 0.f);
                    const float* wr = Wr2s + col*8;
                    #pragma unroll
                    for (int e = 0; e < NEXP; e++) lp[e] += r * wr[e];
                }
            #pragma unroll
            for (int off = 1; off < 4; off <<= 1)
                #pragma unroll
                for (int e = 0; e < NEXP; e++) lp[e] += __shfl_xor_sync(0xFFFFFFFFu, lp[e], off);
            if ((lane & 3) == 0 && node < NN) {
                #pragma unroll
                for (int e = 0; e < NEXP; e++) atomicAdd(&lgpS[rloc*8 + e], lp[e]);
            }
        }
    __syncthreads();

    if (t < 128) {
        int node = mbase + t;
        if (node < NN) {
            float v0 = lgpS[t*8 + 0] + br2[0];
            int best = 0; float bv = v0, second = -1e30f;
            #pragma unroll
            for (int e = 1; e < NEXP; e++) {
                float v = lgpS[t*8 + e] + br2[e];
                if (v > bv) { second = bv; bv = v; best = e; }
                else if (v > second) second = v;
            }
            g_idx[node] = best;
            if (bv - second < 1e-3f * fmaxf(fabsf(bv), 1.f)) {
                int pos = atomicAdd(&g_fixn, 1);
                if (pos < FIXCAP) g_fixlist[pos] = node;
            }
        }
    }
}

// ---------------- exact fp32 fixup for near-tie nodes ----------------
__global__ void fixup_kernel(const float* __restrict__ Wr1, const float* __restrict__ br1,
                             const float* __restrict__ Wr2, const float* __restrict__ br2) {
    int nwarps = (gridDim.x * blockDim.x) >> 5;
    int w = (blockIdx.x * blockDim.x + threadIdx.x) >> 5;
    int lane = threadIdx.x & 31;
    int n = g_fixn; if (n > FIXCAP) n = FIXCAP;
    for (int f = w; f < n; f += nwarps) {
        int node = g_fixlist[f];
        float hreg[8];
        #pragma unroll
        for (int j = 0; j < 8; j++) hreg[j] = g_h[(size_t)node*HD + j*32 + lane];
        float r[8];
        #pragma unroll
        for (int j = 0; j < 8; j++) r[j] = 0.f;
        for (int k = 0; k < 256; k++) {
            float hk = __shfl_sync(0xFFFFFFFFu, hreg[k >> 5], k & 31);
            const float* wrow = Wr1 + (size_t)k*HD + lane;
            #pragma unroll
            for (int j = 0; j < 8; j++) r[j] += hk * wrow[j*32];
        }
        float sf0 = g_sf[2*node], sf1 = g_sf[2*node + 1];
        float lp[NEXP];
        #pragma unroll
        for (int e = 0; e < NEXP; e++) lp[e] = 0.f;
        #pragma unroll
        for (int j = 0; j < 8; j++) {
            int col = j*32 + lane;
            float rv = r[j] + sf0*Wr1[256*HD + col] + sf1*Wr1[257*HD + col] + br1[col];
            rv = fmaxf(rv, 0.f);
            #pragma unroll
            for (int e = 0; e < NEXP; e++) lp[e] += rv * Wr2[col*8 + e];
        }
        #pragma unroll
        for (int off = 16; off > 0; off >>= 1)
            #pragma unroll
            for (int e = 0; e < NEXP; e++) lp[e] += __shfl_xor_sync(0xFFFFFFFFu, lp[e], off);
        if (lane == 0) {
            int best = 0; float bv = lp[0] + br2[0];
            #pragma unroll
            for (int e = 1; e < NEXP; e++) {
                float v = lp[e] + br2[e];
                if (v > bv) { bv = v; best = e; }
            }
            g_idx[node] = best;
        }
    }
}

// ---------------- bucket nodes by expert (padded to 128) ----------------
__global__ void bucket_count_kernel() {
    __shared__ int sc[NEXP];
    if (threadIdx.x < NEXP) sc[threadIdx.x] = 0;
    __syncthreads();
    int stride = gridDim.x * blockDim.x;
    for (int i = blockIdx.x * blockDim.x + threadIdx.x; i < NN; i += stride)
        atomicAdd(&sc[g_idx[i]], 1);
    __syncthreads();
    if (threadIdx.x < NEXP) atomicAdd(&g_cnt[threadIdx.x], sc[threadIdx.x]);
}

__global__ void bucket_scan_kernel() {
    if (threadIdx.x == 0 && blockIdx.x == 0) {
        int off = 0;
        for (int e = 0; e < NEXP; e++) {
            g_poff[e] = off;
            g_cursor[e] = off;
            off += ((g_cnt[e] + 127) / 128) * 128;
        }
        g_poff[NEXP] = off;
    }
}

__global__ void bucket_scatter_kernel() {
    int stride = gridDim.x * blockDim.x;
    for (int i = blockIdx.x * blockDim.x + threadIdx.x; i < NN; i += stride) {
        int pos = atomicAdd(&g_cursor[g_idx[i]], 1);
        g_list[pos] = i;
    }
}

// ---------------- fp16 2-term tensor-core GEMM, 512 threads, expert-range ----------
#define STGSZ 32768          /* per-stage: Ahi 8K | Alo 8K | B 16K */
#define NSTG 3
#define OFF_ROWS 98304
#define OFF_BIAS 98816
#define DSMEM    99840

__device__ __forceinline__ void issue_loads(uint32_t sb, int stage, int kt, int layer, int e,
                                            const int* rowsS, int t) {
    uint32_t stg = sb + stage*STGSZ;
    #pragma unroll
    for (int q = 0; q < 2; q++) {     // A hi+lo: 1024 x 16B over 512 threads
        int lin = q*512 + t;
        int split = lin >> 9;
        int rem = lin & 511;
        int row = rem >> 2, ch = rem & 3;
        int node = rowsS[row]; if (node < 0) node = 0;
        const __half* src;
        if (layer == 0) {
            src = (split ? gA1lo : gA1hi) + (size_t)node*K2 + kt*32 + ch*8;
        } else {
            int k0 = kt*32;
            if (k0 < 256) src = (split ? gZlo : gZhi) + ((size_t)e*NN + node)*HD + k0 + ch*8;
            else          src = (split ? gG2lo : gG2hi) + (size_t)node*HD + (k0 - 256) + ch*8;
        }
        CP16(stg + split*8192 + sw64(row, ch), src);
    }
    #pragma unroll
    for (int q = 0; q < 2; q++) {     // B: 1024 x 16B over 512 threads
        int lin = q*512 + t;
        int n = lin >> 2, ch = lin & 3;
        const __half* src = g_w16
            + ((size_t)((layer*NEXP + e)*256 + n))*K2 + kt*32 + ch*8;
        CP16(stg + 16384 + sw64(n, ch), src);
    }
    CP_COMMIT();
}

__global__ void __launch_bounds__(512, 1) moe_mma_kernel(
    const float* __restrict__ bias_base, int layer, int e0,
    float* __restrict__ outL2) {
    extern __shared__ char smem[];
    uint32_t sb = smem_u32(smem);
    int t = threadIdx.x;
    int* rowsS = (int*)(smem + OFF_ROWS);
    float* biasS = (float*)(smem + OFF_BIAS);

    int e;
    if (layer == 0) {
        e = e0 + (blockIdx.x & 3);          // 4-expert-inner: A tile L2-shared
        int mtile = blockIdx.x >> 2;
        if (t < 128) {
            int m = mtile * 128 + t;
            rowsS[t] = (m < NN) ? m : -1;
        }
    } else {
        int mstart = g_poff[e0];
        int mb = mstart + blockIdx.x * 128;
        if (mb >= g_poff[e0 + 4]) return;
        int ee = e0;
        while (mb >= g_poff[ee + 1]) ee++;
        e = ee;
        if (t < 128) rowsS[t] = g_list[mb + t];
    }
    if (t < 256) biasS[t] = bias_base[e*HD + t];
    __syncthreads();

    float acc[4][4][4];
    #pragma unroll
    for (int mf = 0; mf < 4; mf++)
        #pragma unroll
        for (int nf = 0; nf < 4; nf++)
            #pragma unroll
            for (int c = 0; c < 4; c++) acc[mf][nf][c] = 0.f;

    int lane = t & 31, wid = t >> 5;
    int m0 = (wid >> 3) * 64;      // 2 m-warps
    int n0 = (wid & 7) * 32;       // 8 n-warps

    issue_loads(sb, 0, 0, layer, e, rowsS, t);
    issue_loads(sb, 1, 1, layer, e, rowsS, t);
    issue_loads(sb, 2, 2, layer, e, rowsS, t);

    for (int kt = 0; kt < 16; kt++) {
        CP_WAIT2();
        __syncthreads();
        uint32_t stg = sb + (kt % NSTG)*STGSZ;
        #pragma unroll
        for (int k16 = 0; k16 < 2; k16++) {
            uint32_t aF[4][4], bF[2][4];
            int akk = k16*16 + (lane >> 4)*8;
            int arow = lane & 15;
            int bg = lane >> 3, brr = lane & 7;
            int bkk = k16*16 + (bg & 1)*8;
            #pragma unroll
            for (int nf2 = 0; nf2 < 2; nf2++) {
                int row = n0 + nf2*16 + ((bg >> 1) & 1)*8 + brr;
                LDSM4(bF[nf2][0], bF[nf2][1], bF[nf2][2], bF[nf2][3],
                      stg + 16384 + sw64(row, bkk >> 3));
            }
            #pragma unroll
            for (int mf = 0; mf < 4; mf++) {
                int row = m0 + mf*16 + arow;
                LDSM4(aF[mf][0], aF[mf][1], aF[mf][2], aF[mf][3], stg + sw64(row, akk >> 3));
            }
            mma_all4(acc, aF, bF);                       // Ahi * B
            #pragma unroll
            for (int mf = 0; mf < 4; mf++) {
                int row = m0 + mf*16 + arow;
                LDSM4(aF[mf][0], aF[mf][1], aF[mf][2], aF[mf][3], stg + 8192 + sw64(row, akk >> 3));
            }
            mma_all4(acc, aF, bF);                       // Alo * B
        }
        __syncthreads();
        if (kt + NSTG < 16) issue_loads(sb, kt % NSTG, kt + NSTG, layer, e, rowsS, t);
        else CP_COMMIT();
    }

    // ---------------- epilogue ----------------
    if (layer == 0) {
        #pragma unroll
        for (int mf = 0; mf < 4; mf++)
            #pragma unroll
            for (int p = 0; p < 2; p++) {
                int row = m0 + mf*16 + (lane >> 2) + p*8;
                int node = rowsS[row];
                if (node < 0) continue;
                size_t base = ((size_t)e*NN + node)*HD;
                #pragma unroll
                for (int nf = 0; nf < 4; nf++) {
                    int col = n0 + nf*8 + (lane & 3)*2;
                    float z0 = fmaxf(acc[mf][nf][p*2+0] + biasS[col],     0.f);
                    float z1 = fmaxf(acc[mf][nf][p*2+1] + biasS[col + 1], 0.f);
                    *(uint32_t*)(gZhi + base + col) = pack2(z0, z1);
                    *(uint32_t*)(gZlo + base + col) = pack_lo2(z0, z1);
                }
            }
    } else {
        #pragma unroll
        for (int mf = 0; mf < 4; mf++)
            #pragma unroll
            for (int p = 0; p < 2; p++) {
                int row = m0 + mf*16 + (lane >> 2) + p*8;
                int node = rowsS[row];
                if (node < 0) continue;
                float* orow = outL2 + (size_t)node*HD;
                #pragma unroll
                for (int nf = 0; nf < 4; nf++) {
                    int col = n0 + nf*8 + (lane & 3)*2;
                    float o0 = acc[mf][nf][p*2+0] + biasS[col];
                    float o1 = acc[mf][nf][p*2+1] + biasS[col + 1];
                    *(float2*)(orow + col) = make_float2(o0, o1);
                }
            }
    }
}

// ---------------- launch: R14 schedule (split tail) + fast 3-phase scan ------------
extern "C" void kernel_launch(void* const* d_in, const int* in_sizes, int n_in,
                              void* d_out, int out_size) {
    (void)in_sizes; (void)n_in; (void)out_size;
    const float* x     = (const float*)d_in[0];
    const void*  ei    = d_in[1];
    const void*  batch = d_in[2];
    const float* W_enc = (const float*)d_in[3];
    const float* b_enc = (const float*)d_in[4];
    const float* Wr1   = (const float*)d_in[5];
    const float* br1   = (const float*)d_in[6];
    const float* Wr2   = (const float*)d_in[7];
    const float* br2   = (const float*)d_in[8];
    const float* Ws0   = (const float*)d_in[9];
    const float* Wn0   = (const float*)d_in[10];
    const float* b0    = (const float*)d_in[11];
    const float* Ws1   = (const float*)d_in[12];
    const float* Wn1   = (const float*)d_in[13];
    const float* b1    = (const float*)d_in[14];
    float* out = (float*)d_out;

    static cudaStream_t s1 = nullptr;
    static cudaEvent_t evStart, evEnc, evW, evB, evZa, evDone;
    if (!s1) {
        cudaStreamCreateWithFlags(&s1, cudaStreamNonBlocking);
        cudaEventCreateWithFlags(&evStart, cudaEventDisableTiming);
        cudaEventCreateWithFlags(&evEnc,   cudaEventDisableTiming);
        cudaEventCreateWithFlags(&evW,     cudaEventDisableTiming);
        cudaEventCreateWithFlags(&evB,     cudaEventDisableTiming);
        cudaEventCreateWithFlags(&evZa,    cudaEventDisableTiming);
        cudaEventCreateWithFlags(&evDone,  cudaEventDisableTiming);
        cudaFuncSetAttribute(moe_mma_kernel,
                             cudaFuncAttributeMaxDynamicSharedMemorySize, DSMEM);
        cudaFuncSetAttribute(router_mma_kernel,
                             cudaFuncAttributeMaxDynamicSharedMemorySize, R2_DSMEM);
    }

    // fork: side stream does weight prep immediately
    cudaEventRecord(evStart, 0);
    cudaStreamWaitEvent(s1, evStart, 0);
    wprep_kernel<<<2048, 256, 0, s1>>>(Ws0, Wn0, Ws1, Wn1);
    cudaEventRecord(evW, s1);
    wr1prep_kernel<<<256, 256, 0, s1>>>(Wr1);

    // main stream: init -> convert(+hist) -> encoder
    detect_kernel<<<1, 32>>>((const unsigned int*)ei);
    init_kernel<<<512, 256>>>();
    convert_kernel<<<2048, 256>>>(ei, batch);
    encoder_kernel<<<2048, 256>>>(x, W_enc, b_enc);
    cudaEventRecord(evEnc, 0);

    // side stream: tensor router chain (hidden under CSR + aggh + GEMM1)
    cudaStreamWaitEvent(s1, evEnc, 0);
    counts_kernel<<<512, 256, 0, s1>>>();
    sf_kernel<<<256, 256, 0, s1>>>();
    router_mma_kernel<<<MT, 512, R2_DSMEM, s1>>>(Wr1, br1, Wr2, br2);
    fixup_kernel<<<64, 256, 0, s1>>>(Wr1, br1, Wr2, br2);
    bucket_count_kernel<<<512, 256, 0, s1>>>();
    bucket_scan_kernel<<<1, 1, 0, s1>>>();
    bucket_scatter_kernel<<<256, 256, 0, s1>>>();
    cudaEventRecord(evB, s1);

    // main stream: fast 3-phase CSR + aggh (overlaps router chain)
    scan_part_kernel<<<NBS, 512>>>();
    scan_top_kernel<<<1, 128>>>();
    scan_apply_kernel<<<NBS, 512>>>();
    scatter_kernel<<<1024, 256>>>();
    aggh_kernel<<<6250, 256>>>();

    // main: layer-1 first half (experts 0-3), then second half
    cudaStreamWaitEvent(0, evW, 0);
    moe_mma_kernel<<<MT*4, 512, DSMEM>>>(b0, 0, 0, nullptr);
    cudaEventRecord(evZa, 0);
    moe_mma_kernel<<<MT*4, 512, DSMEM>>>(b0, 0, 4, nullptr);

    // side: aggz + GEMM2 for experts 0-3 (overlaps GEMM1 second half)
    cudaStreamWaitEvent(s1, evZa, 0);
    aggz_kernel<<<3000, 256, 0, s1>>>(0, 4);
    moe_mma_kernel<<<400, 512, DSMEM, s1>>>(b1, 1, 0, out);
    cudaEventRecord(evDone, s1);

    // main: aggz + GEMM2 for experts 4-7
    cudaStreamWaitEvent(0, evB, 0);
    aggz_kernel<<<3000, 256>>>(4, 8);
    moe_mma_kernel<<<400, 512, DSMEM>>>(b1, 1, 4, out);

    // join: main must not retire before side's GEMM2a (harness reads out)
    cudaStreamWaitEvent(0, evDone, 0);
}